// round 7
// baseline (speedup 1.0000x reference)
#include <cuda_runtime.h>
#include <cstddef>

// Problem dims
#define T_STEPS 16
#define B_DIM   64
#define S_DIM   512
#define H_DIM   2048
#define A_DIM   32
#define MROWS   (T_STEPS * B_DIM)          // 1024
#define NELEM   ((size_t)MROWS * H_DIM)    // 2,097,152
#define MBIG    (T_STEPS * MROWS)          // 16384

// Output layout: concat of (value, action, m1, m2, m_act, m_crit), fp32
#define OFF_VALUE  0
#define OFF_ACTION 1024
#define OFF_M1     33792
#define OFF_M2     2130944
#define OFF_MACT   4228096
#define OFF_MCRIT  4260864

// Scratch (device globals: allocation-free per harness rules)
__device__ float g_cur1[MROWS * H_DIM];                    // 8 MB
__device__ float g_S1[(size_t)T_STEPS * MROWS * H_DIM];    // 128 MB
__device__ float g_H[(size_t)T_STEPS * MROWS * H_DIM];     // 128 MB
__device__ float g_S2[MROWS * H_DIM];                      // 8 MB

// ---------------------------------------------------------------------------
// Packed f32x2 helpers
// ---------------------------------------------------------------------------
__device__ __forceinline__ unsigned long long pack2(float x, float y) {
    unsigned long long r;
    asm("mov.b64 %0, {%1, %2};" : "=l"(r) : "f"(x), "f"(y));
    return r;
}
__device__ __forceinline__ void fma2(unsigned long long& acc,
                                     unsigned long long a,
                                     unsigned long long b) {
    asm("fma.rn.f32x2 %0, %1, %2, %0;" : "+l"(acc) : "l"(a), "l"(b));
}
__device__ __forceinline__ void add2(unsigned long long& a,
                                     unsigned long long b) {
    asm("add.rn.f32x2 %0, %0, %1;" : "+l"(a) : "l"(b));
}
__device__ __forceinline__ float2 unpack2(unsigned long long v) {
    float2 f;
    asm("mov.b64 {%0, %1}, %2;" : "=f"(f.x), "=f"(f.y) : "l"(v));
    return f;
}

// ---------------------------------------------------------------------------
// NT SGEMM for cur1 — BIT-EXACT chain proven (m1=0 since round 3). Unchanged.
// ---------------------------------------------------------------------------
__global__ __launch_bounds__(256) void sgemm_nt(
    const float* __restrict__ A, const float* __restrict__ B,
    const float* __restrict__ bias, float* __restrict__ C,
    int M, int N, int K)
{
    __shared__ float As[8][128];
    __shared__ float Bs[8][128];

    const int tid = threadIdx.x;
    const int bm = blockIdx.y * 128;
    const int bn = blockIdx.x * 128;

    const int lrow = tid >> 1;
    const int lcol = (tid & 1) * 4;

    const int tx = tid & 15;
    const int ty = tid >> 4;

    unsigned long long acc[8][4];
#pragma unroll
    for (int i = 0; i < 8; i++)
#pragma unroll
        for (int j = 0; j < 4; j++) acc[i][j] = 0ULL;

    const float* Aptr = A + (size_t)(bm + lrow) * K + lcol;
    const float* Bptr = B + (size_t)(bn + lrow) * K + lcol;

    for (int k0 = 0; k0 < K; k0 += 8) {
        float4 a4 = *(const float4*)(Aptr + k0);
        float4 b4 = *(const float4*)(Bptr + k0);
        As[lcol + 0][lrow] = a4.x; As[lcol + 1][lrow] = a4.y;
        As[lcol + 2][lrow] = a4.z; As[lcol + 3][lrow] = a4.w;
        Bs[lcol + 0][lrow] = b4.x; Bs[lcol + 1][lrow] = b4.y;
        Bs[lcol + 2][lrow] = b4.z; Bs[lcol + 3][lrow] = b4.w;
        __syncthreads();

#pragma unroll
        for (int k = 0; k < 8; k++) {
            float ar[8];
            float4 t;
            t = *(const float4*)&As[k][ty * 8];     ar[0]=t.x; ar[1]=t.y; ar[2]=t.z; ar[3]=t.w;
            t = *(const float4*)&As[k][ty * 8 + 4]; ar[4]=t.x; ar[5]=t.y; ar[6]=t.z; ar[7]=t.w;
            float4 b0 = *(const float4*)&Bs[k][tx * 8];
            float4 b1 = *(const float4*)&Bs[k][tx * 8 + 4];
            unsigned long long bp[4];
            bp[0] = pack2(b0.x, b0.y); bp[1] = pack2(b0.z, b0.w);
            bp[2] = pack2(b1.x, b1.y); bp[3] = pack2(b1.z, b1.w);
#pragma unroll
            for (int i = 0; i < 8; i++) {
                unsigned long long ap = pack2(ar[i], ar[i]);
#pragma unroll
                for (int j = 0; j < 4; j++)
                    fma2(acc[i][j], ap, bp[j]);
            }
        }
        __syncthreads();
    }

    const int row0 = bm + ty * 8;
    const int col0 = bn + tx * 8;
#pragma unroll
    for (int i = 0; i < 8; i++) {
#pragma unroll
        for (int jv = 0; jv < 2; jv++) {
            float2 p0 = unpack2(acc[i][jv * 2 + 0]);
            float2 p1 = unpack2(acc[i][jv * 2 + 1]);
            float4 v;
            v.x = __fadd_rn(p0.x, bias[col0 + jv * 4 + 0]);
            v.y = __fadd_rn(p0.y, bias[col0 + jv * 4 + 1]);
            v.z = __fadd_rn(p1.x, bias[col0 + jv * 4 + 2]);
            v.w = __fadd_rn(p1.y, bias[col0 + jv * 4 + 3]);
            *(float4*)(C + (size_t)(row0 + i) * N + col0 + jv * 4) = v;
        }
    }
}

// ---------------------------------------------------------------------------
// 4-way K-sliced NT SGEMM, zero-MOV FFMA2 dataflow.
// Rounding recipe (PROVEN round 5): P_s = ascending-k FMA chain per 512-slice,
// C = (((P0+P1)+P2)+P3) + bias. FFMA2 lanes pair adjacent m-rows; per-lane
// fp32 rounding identical to scalar.
// A pairs come straight from As via LDS.128; B pairs come from a DUPLICATED
// smem tile (each value stored twice) via LDS.128. No pack MOVs in the loop.
// BM=128, BN=64, BK=16, per thread 8m x 4n (4 m-pairs), 256 threads.
// ---------------------------------------------------------------------------
#define SPLIT_TILE_LOOP(KSTART, KEND, ACC)                                    \
    for (int k0 = (KSTART); k0 < (KEND); k0 += 16) {                          \
        {                                                                     \
            float4 a4 = *(const float4*)(Aptr + k0);                          \
            float4 a4b = *(const float4*)(Aptr + k0 + 4);                     \
            As[ak + 0][arow] = a4.x;  As[ak + 1][arow] = a4.y;                \
            As[ak + 2][arow] = a4.z;  As[ak + 3][arow] = a4.w;                \
            As[ak + 4][arow] = a4b.x; As[ak + 5][arow] = a4b.y;               \
            As[ak + 6][arow] = a4b.z; As[ak + 7][arow] = a4b.w;               \
            float4 b4 = *(const float4*)(Bptr + k0);                          \
            ((float2*)Bsd[bk + 0])[brow] = make_float2(b4.x, b4.x);           \
            ((float2*)Bsd[bk + 1])[brow] = make_float2(b4.y, b4.y);           \
            ((float2*)Bsd[bk + 2])[brow] = make_float2(b4.z, b4.z);           \
            ((float2*)Bsd[bk + 3])[brow] = make_float2(b4.w, b4.w);           \
        }                                                                     \
        __syncthreads();                                                      \
        _Pragma("unroll")                                                     \
        for (int k = 0; k < 16; k++) {                                        \
            const ulonglong2* aptr2 = (const ulonglong2*)&As[k][ty * 8];      \
            ulonglong2 aA = aptr2[0];  /* (m0,m1),(m2,m3) */                  \
            ulonglong2 aB = aptr2[1];  /* (m4,m5),(m6,m7) */                  \
            const ulonglong2* bptr2 = (const ulonglong2*)&Bsd[k][tx * 8];     \
            ulonglong2 bA = bptr2[0];  /* (n0,n0),(n1,n1) */                  \
            ulonglong2 bB = bptr2[1];  /* (n2,n2),(n3,n3) */                  \
            fma2(ACC[0][0], aA.x, bA.x); fma2(ACC[0][1], aA.x, bA.y);         \
            fma2(ACC[0][2], aA.x, bB.x); fma2(ACC[0][3], aA.x, bB.y);         \
            fma2(ACC[1][0], aA.y, bA.x); fma2(ACC[1][1], aA.y, bA.y);         \
            fma2(ACC[1][2], aA.y, bB.x); fma2(ACC[1][3], aA.y, bB.y);         \
            fma2(ACC[2][0], aB.x, bA.x); fma2(ACC[2][1], aB.x, bA.y);         \
            fma2(ACC[2][2], aB.x, bB.x); fma2(ACC[2][3], aB.x, bB.y);         \
            fma2(ACC[3][0], aB.y, bA.x); fma2(ACC[3][1], aB.y, bA.y);         \
            fma2(ACC[3][2], aB.y, bB.x); fma2(ACC[3][3], aB.y, bB.y);         \
        }                                                                     \
        __syncthreads();                                                      \
    }

__global__ __launch_bounds__(256) void sgemm_split4_nt(
    const float* __restrict__ A, const float* __restrict__ B,
    const float* __restrict__ bias, float* __restrict__ C,
    int M, int N, int K)
{
    __shared__ float As[16][128];
    __shared__ float Bsd[16][128];   // duplicated: Bsd[k][2n]=Bsd[k][2n+1]=w[n,k]

    const int tid = threadIdx.x;
    const int bm = blockIdx.y * 128;
    const int bn = blockIdx.x * 64;

    const int arow = tid >> 1;          // 0..127
    const int ak   = (tid & 1) * 8;     // 0 or 8
    const int brow = tid >> 2;          // 0..63
    const int bk   = (tid & 3) * 4;     // 0,4,8,12

    const int ty = tid >> 4;            // rows ty*8 (4 m-pairs)
    const int tx = tid & 15;            // cols tx*4

    // acc[p][j]: p = m-pair (rows ty*8+2p, +1), j = n col
    unsigned long long accA[4][4], accB[4][4];
#pragma unroll
    for (int p = 0; p < 4; p++)
#pragma unroll
        for (int j = 0; j < 4; j++) accA[p][j] = 0ULL;

    const float* Aptr = A + (size_t)(bm + arow) * K + ak;
    const float* Bptr = B + (size_t)(bn + brow) * K + bk;

    const int Kq = K >> 2;   // slice length

    // slice 0 -> accA
    SPLIT_TILE_LOOP(0, Kq, accA)

    // slices 1..3 -> accB, fold serially: A = A + B
#pragma unroll 1
    for (int s = 1; s < 4; s++) {
#pragma unroll
        for (int p = 0; p < 4; p++)
#pragma unroll
            for (int j = 0; j < 4; j++) accB[p][j] = 0ULL;
        const int ks = s * Kq;
        const int ke = ks + Kq;
        SPLIT_TILE_LOOP(ks, ke, accB)
#pragma unroll
        for (int p = 0; p < 4; p++)
#pragma unroll
            for (int j = 0; j < 4; j++)
                add2(accA[p][j], accB[p][j]);
    }

    const int row0 = bm + ty * 8;
    const int col0 = bn + tx * 4;
#pragma unroll
    for (int p = 0; p < 4; p++) {
        float2 c0 = unpack2(accA[p][0]);
        float2 c1 = unpack2(accA[p][1]);
        float2 c2 = unpack2(accA[p][2]);
        float2 c3 = unpack2(accA[p][3]);
        float4 vlo, vhi;
        vlo.x = __fadd_rn(c0.x, bias[col0 + 0]);
        vlo.y = __fadd_rn(c1.x, bias[col0 + 1]);
        vlo.z = __fadd_rn(c2.x, bias[col0 + 2]);
        vlo.w = __fadd_rn(c3.x, bias[col0 + 3]);
        vhi.x = __fadd_rn(c0.y, bias[col0 + 0]);
        vhi.y = __fadd_rn(c1.y, bias[col0 + 1]);
        vhi.z = __fadd_rn(c2.y, bias[col0 + 2]);
        vhi.w = __fadd_rn(c3.y, bias[col0 + 3]);
        *(float4*)(C + (size_t)(row0 + 2 * p + 0) * N + col0) = vlo;
        *(float4*)(C + (size_t)(row0 + 2 * p + 1) * N + col0) = vhi;
    }
}

// ---------------------------------------------------------------------------
// m1 scan (BIT-EXACT — do not touch)
// ---------------------------------------------------------------------------
__global__ void k_scan1(const float* __restrict__ cur1,
                        const float* __restrict__ mem1,
                        const float* __restrict__ beta1p,
                        float* __restrict__ m1_out,
                        float* __restrict__ S1)
{
    size_t e = (size_t)blockIdx.x * blockDim.x + threadIdx.x;
    if (e >= NELEM) return;
    const float beta = *beta1p;
    const float c = cur1[e];
    float m = mem1[e];
#pragma unroll
    for (int k = 0; k < T_STEPS; k++) {
        float reset = (m > 1.0f) ? 1.0f : 0.0f;
        m = __fsub_rn(fmaf(beta, m, c), reset);
        S1[(size_t)k * NELEM + e] = (m > 1.0f) ? 1.0f : 0.0f;
    }
    m1_out[e] = m;
}

// ---------------------------------------------------------------------------
// m2 scan over precomputed h_k (b2 folded in by the GEMM), FMA form.
// ---------------------------------------------------------------------------
__global__ void k_scan2(const float* __restrict__ Hbuf,
                        const float* __restrict__ mem2,
                        const float* __restrict__ beta2p,
                        float* __restrict__ m2_out,
                        float* __restrict__ S2)
{
    size_t e = (size_t)blockIdx.x * blockDim.x + threadIdx.x;
    if (e >= NELEM) return;
    const float beta = *beta2p;
    float m = mem2[e];
#pragma unroll
    for (int k = 0; k < T_STEPS; k++) {
        float h = Hbuf[(size_t)k * NELEM + e];
        float reset = (m > 1.0f) ? 1.0f : 0.0f;
        m = __fsub_rn(fmaf(beta, m, h), reset);
    }
    m2_out[e] = m;
    S2[e] = (m > 1.0f) ? 1.0f : 0.0f;
}

// ---------------------------------------------------------------------------
// Heads: value/action + leaky epilogues (FMA form). One block per row.
// ---------------------------------------------------------------------------
__global__ __launch_bounds__(256) void k_heads(
    const float* __restrict__ S2,
    const float* __restrict__ Wc, const float* __restrict__ bc,
    const float* __restrict__ Wa, const float* __restrict__ ba,
    const float* __restrict__ mem_act, const float* __restrict__ mem_crit,
    const float* __restrict__ beta_critp, const float* __restrict__ beta_actp,
    float* __restrict__ out)
{
    const int i = blockIdx.x;
    __shared__ float row[H_DIM];
    for (int h = threadIdx.x; h < H_DIM; h += blockDim.x)
        row[h] = S2[(size_t)i * H_DIM + h];
    __syncthreads();

    float acc[33];
#pragma unroll
    for (int a = 0; a < 33; a++) acc[a] = 0.0f;

    for (int h = threadIdx.x; h < H_DIM; h += blockDim.x) {
        float s = row[h];
        if (s != 0.0f) {
            acc[0] += Wc[h];
#pragma unroll
            for (int a = 0; a < 32; a++)
                acc[a + 1] += Wa[(size_t)a * H_DIM + h];
        }
    }

#pragma unroll
    for (int a = 0; a < 33; a++)
#pragma unroll
        for (int off = 16; off > 0; off >>= 1)
            acc[a] += __shfl_xor_sync(0xFFFFFFFFu, acc[a], off);

    __shared__ float part[8][33];
    const int wid = threadIdx.x >> 5, lane = threadIdx.x & 31;
    if (lane == 0) {
#pragma unroll
        for (int a = 0; a < 33; a++) part[wid][a] = acc[a];
    }
    __syncthreads();

    if (threadIdx.x < 33) {
        const int a = threadIdx.x;
        float y = 0.0f;
#pragma unroll
        for (int w = 0; w < 8; w++) y += part[w][a];
        if (a == 0) {
            y = __fadd_rn(y, bc[0]);
            const float beta = *beta_critp;
            float mem = mem_crit[i];
            float reset = (mem > 1.0f) ? 1.0f : 0.0f;
            float m = __fsub_rn(fmaf(beta, mem, y), reset);
            out[OFF_VALUE + i] = (m > 1.0f) ? 1.0f : 0.0f;
            out[OFF_MCRIT + i] = m;
        } else {
            const int j = a - 1;
            y = __fadd_rn(y, ba[j]);
            const float beta = *beta_actp;
            float mem = mem_act[(size_t)i * A_DIM + j];
            float reset = (mem > 1.0f) ? 1.0f : 0.0f;
            float m = __fsub_rn(fmaf(beta, mem, y), reset);
            out[OFF_ACTION + (size_t)i * A_DIM + j] = (m > 1.0f) ? 1.0f : 0.0f;
            out[OFF_MACT + (size_t)i * A_DIM + j] = m;
        }
    }
}

// ---------------------------------------------------------------------------
extern "C" void kernel_launch(void* const* d_in, const int* in_sizes, int n_in,
                              void* d_out, int out_size)
{
    const float* inputs   = (const float*)d_in[0];
    const float* mem1     = (const float*)d_in[1];
    const float* mem2     = (const float*)d_in[2];
    const float* mem_act  = (const float*)d_in[3];
    const float* mem_crit = (const float*)d_in[4];
    const float* W1 = (const float*)d_in[5];
    const float* b1 = (const float*)d_in[6];
    const float* W2 = (const float*)d_in[7];
    const float* b2 = (const float*)d_in[8];
    const float* Wc = (const float*)d_in[9];
    const float* bc = (const float*)d_in[10];
    const float* Wa = (const float*)d_in[11];
    const float* ba = (const float*)d_in[12];
    const float* beta1     = (const float*)d_in[13];
    const float* beta2     = (const float*)d_in[14];
    const float* beta_crit = (const float*)d_in[15];
    const float* beta_act  = (const float*)d_in[16];
    float* out = (float*)d_out;

    float *cur1, *S1, *Hb, *S2;
    cudaGetSymbolAddress((void**)&cur1, g_cur1);
    cudaGetSymbolAddress((void**)&S1, g_S1);
    cudaGetSymbolAddress((void**)&Hb, g_H);
    cudaGetSymbolAddress((void**)&S2, g_S2);

    // 1) cur1 = inputs @ W1^T + b1 (bit-exact chain)
    sgemm_nt<<<dim3(H_DIM / 128, MROWS / 128), 256>>>(
        inputs, W1, b1, cur1, MROWS, H_DIM, S_DIM);

    // 2) m1 scan -> S1 spikes (bit-exact path)
    k_scan1<<<(unsigned)((NELEM + 255) / 256), 256>>>(
        cur1, mem1, beta1, out + OFF_M1, S1);

    // 3) fused big GEMM, sliced1x4 rounding, zero-MOV FFMA2: H = S1 @ W2^T + b2
    sgemm_split4_nt<<<dim3(H_DIM / 64, MBIG / 128), 256>>>(
        S1, W2, b2, Hb, MBIG, H_DIM, H_DIM);

    // 4) m2 scan -> m2 final, S2 spikes
    k_scan2<<<(unsigned)((NELEM + 255) / 256), 256>>>(
        Hb, mem2, beta2, out + OFF_M2, S2);

    // 5) heads
    k_heads<<<MROWS, 256>>>(S2, Wc, bc, Wa, ba, mem_act, mem_crit,
                            beta_crit, beta_act, out);
}

// round 8
// speedup vs baseline: 1.1746x; 1.1746x over previous
#include <cuda_runtime.h>
#include <cstddef>

// Problem dims
#define T_STEPS 16
#define B_DIM   64
#define S_DIM   512
#define H_DIM   2048
#define A_DIM   32
#define MROWS   (T_STEPS * B_DIM)          // 1024
#define NELEM   ((size_t)MROWS * H_DIM)    // 2,097,152
#define MBIG    (T_STEPS * MROWS)          // 16384
#define KWORDS  (H_DIM / 32)               // 64 bit-words per S1 row

// Output layout: concat of (value, action, m1, m2, m_act, m_crit), fp32
#define OFF_VALUE  0
#define OFF_ACTION 1024
#define OFF_M1     33792
#define OFF_M2     2130944
#define OFF_MACT   4228096
#define OFF_MCRIT  4260864

// Scratch (device globals: allocation-free per harness rules)
__device__ float    g_cur1[MROWS * H_DIM];                   // 8 MB
__device__ unsigned g_S1bits[(size_t)MBIG * KWORDS];         // 4 MB (spike bits)
__device__ float    g_H[(size_t)T_STEPS * MROWS * H_DIM];    // 128 MB
__device__ float    g_S2[MROWS * H_DIM];                     // 8 MB

// ---------------------------------------------------------------------------
// Packed f32x2 helpers
// ---------------------------------------------------------------------------
__device__ __forceinline__ unsigned long long pack2(float x, float y) {
    unsigned long long r;
    asm("mov.b64 %0, {%1, %2};" : "=l"(r) : "f"(x), "f"(y));
    return r;
}
__device__ __forceinline__ void fma2(unsigned long long& acc,
                                     unsigned long long a,
                                     unsigned long long b) {
    asm("fma.rn.f32x2 %0, %1, %2, %0;" : "+l"(acc) : "l"(a), "l"(b));
}
__device__ __forceinline__ void add2(unsigned long long& a,
                                     unsigned long long b) {
    asm("add.rn.f32x2 %0, %0, %1;" : "+l"(a) : "l"(b));
}
__device__ __forceinline__ float2 unpack2(unsigned long long v) {
    float2 f;
    asm("mov.b64 {%0, %1}, %2;" : "=f"(f.x), "=f"(f.y) : "l"(v));
    return f;
}
// Predicated dual packed add: if (bit) { a0 += b0 (2 lanes); a1 += b1 (2 lanes) }
// s=1: round(acc+w) == fma(1,w,acc); s=0: skip == fma(0,w,acc) (acc never -0).
__device__ __forceinline__ void padd2x2(unsigned long long& a0,
                                        unsigned long long& a1,
                                        unsigned bit,
                                        unsigned long long b0,
                                        unsigned long long b1) {
    asm("{\n\t"
        ".reg .pred p;\n\t"
        "setp.ne.u32 p, %2, 0;\n\t"
        "@p add.rn.f32x2 %0, %0, %3;\n\t"
        "@p add.rn.f32x2 %1, %1, %4;\n\t"
        "}"
        : "+l"(a0), "+l"(a1)
        : "r"(bit), "l"(b0), "l"(b1));
}

// ---------------------------------------------------------------------------
// NT SGEMM for cur1 — BIT-EXACT (m1=0 proven rounds 3-7). Unchanged (round 6).
// ---------------------------------------------------------------------------
__global__ __launch_bounds__(256) void sgemm_nt(
    const float* __restrict__ A, const float* __restrict__ B,
    const float* __restrict__ bias, float* __restrict__ C,
    int M, int N, int K)
{
    __shared__ float As[8][128];
    __shared__ float Bs[8][128];

    const int tid = threadIdx.x;
    const int bm = blockIdx.y * 128;
    const int bn = blockIdx.x * 128;

    const int lrow = tid >> 1;
    const int lcol = (tid & 1) * 4;

    const int tx = tid & 15;
    const int ty = tid >> 4;

    unsigned long long acc[8][4];
#pragma unroll
    for (int i = 0; i < 8; i++)
#pragma unroll
        for (int j = 0; j < 4; j++) acc[i][j] = 0ULL;

    const float* Aptr = A + (size_t)(bm + lrow) * K + lcol;
    const float* Bptr = B + (size_t)(bn + lrow) * K + lcol;

    for (int k0 = 0; k0 < K; k0 += 8) {
        float4 a4 = *(const float4*)(Aptr + k0);
        float4 b4 = *(const float4*)(Bptr + k0);
        As[lcol + 0][lrow] = a4.x; As[lcol + 1][lrow] = a4.y;
        As[lcol + 2][lrow] = a4.z; As[lcol + 3][lrow] = a4.w;
        Bs[lcol + 0][lrow] = b4.x; Bs[lcol + 1][lrow] = b4.y;
        Bs[lcol + 2][lrow] = b4.z; Bs[lcol + 3][lrow] = b4.w;
        __syncthreads();

#pragma unroll
        for (int k = 0; k < 8; k++) {
            float ar[8];
            float4 t;
            t = *(const float4*)&As[k][ty * 8];     ar[0]=t.x; ar[1]=t.y; ar[2]=t.z; ar[3]=t.w;
            t = *(const float4*)&As[k][ty * 8 + 4]; ar[4]=t.x; ar[5]=t.y; ar[6]=t.z; ar[7]=t.w;
            float4 b0 = *(const float4*)&Bs[k][tx * 8];
            float4 b1 = *(const float4*)&Bs[k][tx * 8 + 4];
            unsigned long long bp[4];
            bp[0] = pack2(b0.x, b0.y); bp[1] = pack2(b0.z, b0.w);
            bp[2] = pack2(b1.x, b1.y); bp[3] = pack2(b1.z, b1.w);
#pragma unroll
            for (int i = 0; i < 8; i++) {
                unsigned long long ap = pack2(ar[i], ar[i]);
#pragma unroll
                for (int j = 0; j < 4; j++)
                    fma2(acc[i][j], ap, bp[j]);
            }
        }
        __syncthreads();
    }

    const int row0 = bm + ty * 8;
    const int col0 = bn + tx * 8;
#pragma unroll
    for (int i = 0; i < 8; i++) {
#pragma unroll
        for (int jv = 0; jv < 2; jv++) {
            float2 p0 = unpack2(acc[i][jv * 2 + 0]);
            float2 p1 = unpack2(acc[i][jv * 2 + 1]);
            float4 v;
            v.x = __fadd_rn(p0.x, bias[col0 + jv * 4 + 0]);
            v.y = __fadd_rn(p0.y, bias[col0 + jv * 4 + 1]);
            v.z = __fadd_rn(p1.x, bias[col0 + jv * 4 + 2]);
            v.w = __fadd_rn(p1.y, bias[col0 + jv * 4 + 3]);
            *(float4*)(C + (size_t)(row0 + i) * N + col0 + jv * 4) = v;
        }
    }
}

// ---------------------------------------------------------------------------
// Big GEMM: H = S1(bits) @ W2^T + b2 with PROVEN sliced1x4 rounding:
// P_s = ascending-k chain over [s*512,(s+1)*512); C=(((P0+P1)+P2)+P3)+bias.
// A is binary -> predicated packed adds (no multiplies, no packing MOVs).
// BM=128, BN=64, BK=32, per-thread 8m x 4n (2 n-pairs), 256 threads.
// ---------------------------------------------------------------------------
#define BITS_TILE_LOOP(KSTART, KEND, ACC)                                     \
    for (int k0 = (KSTART); k0 < (KEND); k0 += 32) {                          \
        if (tid < 128)                                                        \
            Asb[tid] = Abits[(size_t)(bm + tid) * KWORDS + (k0 >> 5)];        \
        {                                                                     \
            float4 b0 = *(const float4*)(Bptr + k0);                          \
            float4 b1 = *(const float4*)(Bptr + k0 + 4);                      \
            Bs[koff + 0][nrow] = b0.x; Bs[koff + 1][nrow] = b0.y;             \
            Bs[koff + 2][nrow] = b0.z; Bs[koff + 3][nrow] = b0.w;             \
            Bs[koff + 4][nrow] = b1.x; Bs[koff + 5][nrow] = b1.y;             \
            Bs[koff + 6][nrow] = b1.z; Bs[koff + 7][nrow] = b1.w;             \
        }                                                                     \
        __syncthreads();                                                      \
        unsigned am[8];                                                       \
        _Pragma("unroll")                                                     \
        for (int m = 0; m < 8; m++) am[m] = Asb[ty * 8 + m];                  \
        _Pragma("unroll")                                                     \
        for (int k = 0; k < 32; k++) {                                        \
            float4 b = *(const float4*)&Bs[k][tx * 4];                        \
            unsigned long long bp0 = pack2(b.x, b.y);                         \
            unsigned long long bp1 = pack2(b.z, b.w);                         \
            _Pragma("unroll")                                                 \
            for (int m = 0; m < 8; m++)                                       \
                padd2x2(ACC[m][0], ACC[m][1], am[m] & (1u << k), bp0, bp1);   \
        }                                                                     \
        __syncthreads();                                                      \
    }

__global__ __launch_bounds__(256) void sgemm_bits_split4(
    const unsigned* __restrict__ Abits, const float* __restrict__ B,
    const float* __restrict__ bias, float* __restrict__ C,
    int M, int N, int K)
{
    __shared__ float Bs[32][64];
    __shared__ unsigned Asb[128];

    const int tid = threadIdx.x;
    const int bm = blockIdx.y * 128;
    const int bn = blockIdx.x * 64;

    const int nrow = tid >> 2;           // 0..63 (B row = n)
    const int koff = (tid & 3) * 8;      // 0,8,16,24

    const int ty = tid >> 4;             // rows ty*8..+7
    const int tx = tid & 15;             // cols tx*4..+3

    unsigned long long accA[8][2], accB[8][2];
#pragma unroll
    for (int m = 0; m < 8; m++) { accA[m][0] = 0ULL; accA[m][1] = 0ULL; }

    const float* Bptr = B + (size_t)(bn + nrow) * K + koff;

    const int Kq = K >> 2;   // 512

    // slice 0 -> accA
    BITS_TILE_LOOP(0, Kq, accA)

    // slices 1..3 -> accB, serial fold A = A + B
#pragma unroll 1
    for (int s = 1; s < 4; s++) {
#pragma unroll
        for (int m = 0; m < 8; m++) { accB[m][0] = 0ULL; accB[m][1] = 0ULL; }
        const int ks = s * Kq;
        const int ke = ks + Kq;
        BITS_TILE_LOOP(ks, ke, accB)
#pragma unroll
        for (int m = 0; m < 8; m++) {
            add2(accA[m][0], accB[m][0]);
            add2(accA[m][1], accB[m][1]);
        }
    }

    const int row0 = bm + ty * 8;
    const int col0 = bn + tx * 4;
#pragma unroll
    for (int m = 0; m < 8; m++) {
        float2 p0 = unpack2(accA[m][0]);
        float2 p1 = unpack2(accA[m][1]);
        float4 v;
        v.x = __fadd_rn(p0.x, bias[col0 + 0]);
        v.y = __fadd_rn(p0.y, bias[col0 + 1]);
        v.z = __fadd_rn(p1.x, bias[col0 + 2]);
        v.w = __fadd_rn(p1.y, bias[col0 + 3]);
        *(float4*)(C + (size_t)(row0 + m) * N + col0) = v;
    }
}

// ---------------------------------------------------------------------------
// m1 scan (BIT-EXACT update chain) — now emits spike BITS via warp ballot.
// e = row*2048 + h; lane l <-> h bit l of the 32-bit word (h ascending).
// ---------------------------------------------------------------------------
__global__ void k_scan1(const float* __restrict__ cur1,
                        const float* __restrict__ mem1,
                        const float* __restrict__ beta1p,
                        float* __restrict__ m1_out,
                        unsigned* __restrict__ S1bits)
{
    size_t e = (size_t)blockIdx.x * blockDim.x + threadIdx.x;
    if (e >= NELEM) return;
    const int lane = threadIdx.x & 31;
    const size_t row = e / H_DIM;          // 0..1023
    const size_t wcol = (e % H_DIM) >> 5;  // 0..63
    const float beta = *beta1p;
    const float c = cur1[e];
    float m = mem1[e];
#pragma unroll
    for (int k = 0; k < T_STEPS; k++) {
        float reset = (m > 1.0f) ? 1.0f : 0.0f;
        m = __fsub_rn(fmaf(beta, m, c), reset);
        unsigned w = __ballot_sync(0xFFFFFFFFu, m > 1.0f);
        if (lane == 0)
            S1bits[((size_t)k * MROWS + row) * KWORDS + wcol] = w;
    }
    m1_out[e] = m;
}

// ---------------------------------------------------------------------------
// m2 scan over precomputed h_k (b2 folded in by the GEMM), FMA form.
// ---------------------------------------------------------------------------
__global__ void k_scan2(const float* __restrict__ Hbuf,
                        const float* __restrict__ mem2,
                        const float* __restrict__ beta2p,
                        float* __restrict__ m2_out,
                        float* __restrict__ S2)
{
    size_t e = (size_t)blockIdx.x * blockDim.x + threadIdx.x;
    if (e >= NELEM) return;
    const float beta = *beta2p;
    float m = mem2[e];
#pragma unroll
    for (int k = 0; k < T_STEPS; k++) {
        float h = Hbuf[(size_t)k * NELEM + e];
        float reset = (m > 1.0f) ? 1.0f : 0.0f;
        m = __fsub_rn(fmaf(beta, m, h), reset);
    }
    m2_out[e] = m;
    S2[e] = (m > 1.0f) ? 1.0f : 0.0f;
}

// ---------------------------------------------------------------------------
// Heads: value/action + leaky epilogues (FMA form). One block per row.
// ---------------------------------------------------------------------------
__global__ __launch_bounds__(256) void k_heads(
    const float* __restrict__ S2,
    const float* __restrict__ Wc, const float* __restrict__ bc,
    const float* __restrict__ Wa, const float* __restrict__ ba,
    const float* __restrict__ mem_act, const float* __restrict__ mem_crit,
    const float* __restrict__ beta_critp, const float* __restrict__ beta_actp,
    float* __restrict__ out)
{
    const int i = blockIdx.x;
    __shared__ float row[H_DIM];
    for (int h = threadIdx.x; h < H_DIM; h += blockDim.x)
        row[h] = S2[(size_t)i * H_DIM + h];
    __syncthreads();

    float acc[33];
#pragma unroll
    for (int a = 0; a < 33; a++) acc[a] = 0.0f;

    for (int h = threadIdx.x; h < H_DIM; h += blockDim.x) {
        float s = row[h];
        if (s != 0.0f) {
            acc[0] += Wc[h];
#pragma unroll
            for (int a = 0; a < 32; a++)
                acc[a + 1] += Wa[(size_t)a * H_DIM + h];
        }
    }

#pragma unroll
    for (int a = 0; a < 33; a++)
#pragma unroll
        for (int off = 16; off > 0; off >>= 1)
            acc[a] += __shfl_xor_sync(0xFFFFFFFFu, acc[a], off);

    __shared__ float part[8][33];
    const int wid = threadIdx.x >> 5, lane = threadIdx.x & 31;
    if (lane == 0) {
#pragma unroll
        for (int a = 0; a < 33; a++) part[wid][a] = acc[a];
    }
    __syncthreads();

    if (threadIdx.x < 33) {
        const int a = threadIdx.x;
        float y = 0.0f;
#pragma unroll
        for (int w = 0; w < 8; w++) y += part[w][a];
        if (a == 0) {
            y = __fadd_rn(y, bc[0]);
            const float beta = *beta_critp;
            float mem = mem_crit[i];
            float reset = (mem > 1.0f) ? 1.0f : 0.0f;
            float m = __fsub_rn(fmaf(beta, mem, y), reset);
            out[OFF_VALUE + i] = (m > 1.0f) ? 1.0f : 0.0f;
            out[OFF_MCRIT + i] = m;
        } else {
            const int j = a - 1;
            y = __fadd_rn(y, ba[j]);
            const float beta = *beta_actp;
            float mem = mem_act[(size_t)i * A_DIM + j];
            float reset = (mem > 1.0f) ? 1.0f : 0.0f;
            float m = __fsub_rn(fmaf(beta, mem, y), reset);
            out[OFF_ACTION + (size_t)i * A_DIM + j] = (m > 1.0f) ? 1.0f : 0.0f;
            out[OFF_MACT + (size_t)i * A_DIM + j] = m;
        }
    }
}

// ---------------------------------------------------------------------------
extern "C" void kernel_launch(void* const* d_in, const int* in_sizes, int n_in,
                              void* d_out, int out_size)
{
    const float* inputs   = (const float*)d_in[0];
    const float* mem1     = (const float*)d_in[1];
    const float* mem2     = (const float*)d_in[2];
    const float* mem_act  = (const float*)d_in[3];
    const float* mem_crit = (const float*)d_in[4];
    const float* W1 = (const float*)d_in[5];
    const float* b1 = (const float*)d_in[6];
    const float* W2 = (const float*)d_in[7];
    const float* b2 = (const float*)d_in[8];
    const float* Wc = (const float*)d_in[9];
    const float* bc = (const float*)d_in[10];
    const float* Wa = (const float*)d_in[11];
    const float* ba = (const float*)d_in[12];
    const float* beta1     = (const float*)d_in[13];
    const float* beta2     = (const float*)d_in[14];
    const float* beta_crit = (const float*)d_in[15];
    const float* beta_act  = (const float*)d_in[16];
    float* out = (float*)d_out;

    float *cur1, *Hb, *S2;
    unsigned* S1bits;
    cudaGetSymbolAddress((void**)&cur1, g_cur1);
    cudaGetSymbolAddress((void**)&S1bits, g_S1bits);
    cudaGetSymbolAddress((void**)&Hb, g_H);
    cudaGetSymbolAddress((void**)&S2, g_S2);

    // 1) cur1 = inputs @ W1^T + b1 (bit-exact chain)
    sgemm_nt<<<dim3(H_DIM / 128, MROWS / 128), 256>>>(
        inputs, W1, b1, cur1, MROWS, H_DIM, S_DIM);

    // 2) m1 scan -> S1 spike bits (ballot), m1 final
    k_scan1<<<(unsigned)((NELEM + 255) / 256), 256>>>(
        cur1, mem1, beta1, out + OFF_M1, S1bits);

    // 3) fused big GEMM, sliced1x4 rounding, binary-A predicated adds
    sgemm_bits_split4<<<dim3(H_DIM / 64, MBIG / 128), 256>>>(
        S1bits, W2, b2, Hb, MBIG, H_DIM, H_DIM);

    // 4) m2 scan -> m2 final, S2 spikes
    k_scan2<<<(unsigned)((NELEM + 255) / 256), 256>>>(
        Hb, mem2, beta2, out + OFF_M2, S2);

    // 5) heads
    k_heads<<<MROWS, 256>>>(S2, Wc, bc, Wa, ba, mem_act, mem_crit,
                            beta_crit, beta_act, out);
}

// round 9
// speedup vs baseline: 1.2551x; 1.0685x over previous
#include <cuda_runtime.h>
#include <cstddef>

// Problem dims
#define T_STEPS 16
#define B_DIM   64
#define S_DIM   512
#define H_DIM   2048
#define A_DIM   32
#define MROWS   (T_STEPS * B_DIM)          // 1024
#define NELEM   ((size_t)MROWS * H_DIM)    // 2,097,152
#define MBIG    (T_STEPS * MROWS)          // 16384
#define KWORDS  (H_DIM / 32)               // 64 bit-words per S1 row
#define PSTRIDE ((size_t)MBIG * H_DIM)     // one slice-partial plane

// Output layout: concat of (value, action, m1, m2, m_act, m_crit), fp32
#define OFF_VALUE  0
#define OFF_ACTION 1024
#define OFF_M1     33792
#define OFF_M2     2130944
#define OFF_MACT   4228096
#define OFF_MCRIT  4260864

// Scratch (device globals: allocation-free per harness rules)
__device__ float    g_cur1[MROWS * H_DIM];                 // 8 MB
__device__ unsigned g_S1bits[(size_t)MBIG * KWORDS];       // 4 MB spike bits
__device__ float    g_P[(size_t)4 * MBIG * H_DIM];         // 512 MB: 4 slice partials
__device__ float    g_S2[MROWS * H_DIM];                   // 8 MB

// ---------------------------------------------------------------------------
// Packed f32x2 helpers (used by the cur1 GEMM only)
// ---------------------------------------------------------------------------
__device__ __forceinline__ unsigned long long pack2(float x, float y) {
    unsigned long long r;
    asm("mov.b64 %0, {%1, %2};" : "=l"(r) : "f"(x), "f"(y));
    return r;
}
__device__ __forceinline__ void fma2(unsigned long long& acc,
                                     unsigned long long a,
                                     unsigned long long b) {
    asm("fma.rn.f32x2 %0, %1, %2, %0;" : "+l"(acc) : "l"(a), "l"(b));
}
__device__ __forceinline__ float2 unpack2(unsigned long long v) {
    float2 f;
    asm("mov.b64 {%0, %1}, %2;" : "=f"(f.x), "=f"(f.y) : "l"(v));
    return f;
}

// ---------------------------------------------------------------------------
// NT SGEMM for cur1 — BIT-EXACT chain (m1=0 proven rounds 3-8). Unchanged.
// ---------------------------------------------------------------------------
__global__ __launch_bounds__(256) void sgemm_nt(
    const float* __restrict__ A, const float* __restrict__ B,
    const float* __restrict__ bias, float* __restrict__ C,
    int M, int N, int K)
{
    __shared__ float As[8][128];
    __shared__ float Bs[8][128];

    const int tid = threadIdx.x;
    const int bm = blockIdx.y * 128;
    const int bn = blockIdx.x * 128;

    const int lrow = tid >> 1;
    const int lcol = (tid & 1) * 4;

    const int tx = tid & 15;
    const int ty = tid >> 4;

    unsigned long long acc[8][4];
#pragma unroll
    for (int i = 0; i < 8; i++)
#pragma unroll
        for (int j = 0; j < 4; j++) acc[i][j] = 0ULL;

    const float* Aptr = A + (size_t)(bm + lrow) * K + lcol;
    const float* Bptr = B + (size_t)(bn + lrow) * K + lcol;

    for (int k0 = 0; k0 < K; k0 += 8) {
        float4 a4 = *(const float4*)(Aptr + k0);
        float4 b4 = *(const float4*)(Bptr + k0);
        As[lcol + 0][lrow] = a4.x; As[lcol + 1][lrow] = a4.y;
        As[lcol + 2][lrow] = a4.z; As[lcol + 3][lrow] = a4.w;
        Bs[lcol + 0][lrow] = b4.x; Bs[lcol + 1][lrow] = b4.y;
        Bs[lcol + 2][lrow] = b4.z; Bs[lcol + 3][lrow] = b4.w;
        __syncthreads();

#pragma unroll
        for (int k = 0; k < 8; k++) {
            float ar[8];
            float4 t;
            t = *(const float4*)&As[k][ty * 8];     ar[0]=t.x; ar[1]=t.y; ar[2]=t.z; ar[3]=t.w;
            t = *(const float4*)&As[k][ty * 8 + 4]; ar[4]=t.x; ar[5]=t.y; ar[6]=t.z; ar[7]=t.w;
            float4 b0 = *(const float4*)&Bs[k][tx * 8];
            float4 b1 = *(const float4*)&Bs[k][tx * 8 + 4];
            unsigned long long bp[4];
            bp[0] = pack2(b0.x, b0.y); bp[1] = pack2(b0.z, b0.w);
            bp[2] = pack2(b1.x, b1.y); bp[3] = pack2(b1.z, b1.w);
#pragma unroll
            for (int i = 0; i < 8; i++) {
                unsigned long long ap = pack2(ar[i], ar[i]);
#pragma unroll
                for (int j = 0; j < 4; j++)
                    fma2(acc[i][j], ap, bp[j]);
            }
        }
        __syncthreads();
    }

    const int row0 = bm + ty * 8;
    const int col0 = bn + tx * 8;
#pragma unroll
    for (int i = 0; i < 8; i++) {
#pragma unroll
        for (int jv = 0; jv < 2; jv++) {
            float2 p0 = unpack2(acc[i][jv * 2 + 0]);
            float2 p1 = unpack2(acc[i][jv * 2 + 1]);
            float4 v;
            v.x = __fadd_rn(p0.x, bias[col0 + jv * 4 + 0]);
            v.y = __fadd_rn(p0.y, bias[col0 + jv * 4 + 1]);
            v.z = __fadd_rn(p1.x, bias[col0 + jv * 4 + 2]);
            v.w = __fadd_rn(p1.y, bias[col0 + jv * 4 + 3]);
            *(float4*)(C + (size_t)(row0 + i) * N + col0 + jv * 4) = v;
        }
    }
}

// ---------------------------------------------------------------------------
// m1 scan (BIT-EXACT chain) — emits spike bits via ballot (round 8, proven).
// bit l of word wcol <-> h = wcol*32 + l (ascending).
// ---------------------------------------------------------------------------
__global__ void k_scan1(const float* __restrict__ cur1,
                        const float* __restrict__ mem1,
                        const float* __restrict__ beta1p,
                        float* __restrict__ m1_out,
                        unsigned* __restrict__ S1bits)
{
    size_t e = (size_t)blockIdx.x * blockDim.x + threadIdx.x;
    if (e >= NELEM) return;
    const int lane = threadIdx.x & 31;
    const size_t row = e / H_DIM;
    const size_t wcol = (e % H_DIM) >> 5;
    const float beta = *beta1p;
    const float c = cur1[e];
    float m = mem1[e];
#pragma unroll
    for (int k = 0; k < T_STEPS; k++) {
        float reset = (m > 1.0f) ? 1.0f : 0.0f;
        m = __fsub_rn(fmaf(beta, m, c), reset);
        unsigned w = __ballot_sync(0xFFFFFFFFu, m > 1.0f);
        if (lane == 0)
            S1bits[((size_t)k * MROWS + row) * KWORDS + wcol] = w;
    }
    m1_out[e] = m;
}

// ---------------------------------------------------------------------------
// SPARSE big GEMM: per slice s, P_s[m,n] = ascending-k chain of W2[n,k] adds
// over spiking k in [s*512,(s+1)*512). Skipped zeros are bit-equivalent
// (proven: identical rel_err rounds 5-8). One warp per m-row: the spike word
// is warp-uniform -> divergence-free while(word) over set bits only.
// CTA: 512 thr, W2 slice tile [64 n x 512 k] in 132 KB dynamic smem,
// sweeps 512 m-rows. Grid (n/64, M/512, 4 slices).
// ---------------------------------------------------------------------------
#define SM_STRIDE 66   // 64 + 2 pad: conflict-free STS, 8B-aligned float2 LDS

__global__ __launch_bounds__(512) void sgemm_sparse(
    const unsigned* __restrict__ Abits, const float* __restrict__ W2,
    float* __restrict__ P)
{
    extern __shared__ float sm[];        // [512][SM_STRIDE]
    const int tid  = threadIdx.x;
    const int lane = tid & 31;
    const int warp = tid >> 5;
    const int n0    = blockIdx.x * 64;
    const int mbase = blockIdx.y * 512;
    const int s     = blockIdx.z;
    const int ks    = s * 512;

    // Load W2[n0..n0+63][ks..ks+511]: sm[k*SM_STRIDE + r] = W2[n0+r][ks+k]
    for (int i = tid; i < 64 * 512; i += 512) {
        int r = i >> 9;          // 0..63  (row within n-block)
        int k = i & 511;         // 0..511 (k within slice)
        sm[k * SM_STRIDE + r] = W2[(size_t)(n0 + r) * H_DIM + ks + k];
    }
    __syncthreads();

    const float* smk = sm + 2 * lane;                    // lane's n-pair column
    float* Pcol = P + (size_t)s * PSTRIDE + n0 + 2 * lane;

    for (int i = warp; i < 512; i += 16) {
        const int m = mbase + i;
        unsigned bw = 0;
        if (lane < 16)
            bw = Abits[(size_t)m * KWORDS + s * 16 + lane];
        float acc0 = 0.0f, acc1 = 0.0f;
        for (int w = 0; w < 16; w++) {
            unsigned word = __shfl_sync(0xFFFFFFFFu, bw, w);
            const float* smw = smk + (size_t)(w * 32) * SM_STRIDE;
            while (word) {
                int b = __ffs(word) - 1;     // ascending k within word
                word &= word - 1;
                float2 wt = *(const float2*)(smw + (size_t)b * SM_STRIDE);
                acc0 = __fadd_rn(acc0, wt.x);
                acc1 = __fadd_rn(acc1, wt.y);
            }
        }
        *(float2*)(Pcol + (size_t)m * H_DIM) = make_float2(acc0, acc1);
    }
}

// ---------------------------------------------------------------------------
// m2 scan with fused slice merge: h = (((P0+P1)+P2)+P3) + b2  (exact op order
// of the proven epilogue), then the proven FMA-form leaky chain.
// ---------------------------------------------------------------------------
__global__ void k_scan2(const float* __restrict__ P,
                        const float* __restrict__ b2,
                        const float* __restrict__ mem2,
                        const float* __restrict__ beta2p,
                        float* __restrict__ m2_out,
                        float* __restrict__ S2)
{
    size_t e = (size_t)blockIdx.x * blockDim.x + threadIdx.x;
    if (e >= NELEM) return;
    const float beta = *beta2p;
    const float bias = b2[e & (H_DIM - 1)];
    float m = mem2[e];
#pragma unroll
    for (int k = 0; k < T_STEPS; k++) {
        size_t o = (size_t)k * NELEM + e;
        float h = __fadd_rn(P[o], P[PSTRIDE + o]);
        h = __fadd_rn(h, P[2 * PSTRIDE + o]);
        h = __fadd_rn(h, P[3 * PSTRIDE + o]);
        h = __fadd_rn(h, bias);
        float reset = (m > 1.0f) ? 1.0f : 0.0f;
        m = __fsub_rn(fmaf(beta, m, h), reset);
    }
    m2_out[e] = m;
    S2[e] = (m > 1.0f) ? 1.0f : 0.0f;
}

// ---------------------------------------------------------------------------
// Heads: value/action + leaky epilogues (FMA form). One block per row.
// ---------------------------------------------------------------------------
__global__ __launch_bounds__(256) void k_heads(
    const float* __restrict__ S2,
    const float* __restrict__ Wc, const float* __restrict__ bc,
    const float* __restrict__ Wa, const float* __restrict__ ba,
    const float* __restrict__ mem_act, const float* __restrict__ mem_crit,
    const float* __restrict__ beta_critp, const float* __restrict__ beta_actp,
    float* __restrict__ out)
{
    const int i = blockIdx.x;
    __shared__ float row[H_DIM];
    for (int h = threadIdx.x; h < H_DIM; h += blockDim.x)
        row[h] = S2[(size_t)i * H_DIM + h];
    __syncthreads();

    float acc[33];
#pragma unroll
    for (int a = 0; a < 33; a++) acc[a] = 0.0f;

    for (int h = threadIdx.x; h < H_DIM; h += blockDim.x) {
        float s = row[h];
        if (s != 0.0f) {
            acc[0] += Wc[h];
#pragma unroll
            for (int a = 0; a < 32; a++)
                acc[a + 1] += Wa[(size_t)a * H_DIM + h];
        }
    }

#pragma unroll
    for (int a = 0; a < 33; a++)
#pragma unroll
        for (int off = 16; off > 0; off >>= 1)
            acc[a] += __shfl_xor_sync(0xFFFFFFFFu, acc[a], off);

    __shared__ float part[8][33];
    const int wid = threadIdx.x >> 5, lane = threadIdx.x & 31;
    if (lane == 0) {
#pragma unroll
        for (int a = 0; a < 33; a++) part[wid][a] = acc[a];
    }
    __syncthreads();

    if (threadIdx.x < 33) {
        const int a = threadIdx.x;
        float y = 0.0f;
#pragma unroll
        for (int w = 0; w < 8; w++) y += part[w][a];
        if (a == 0) {
            y = __fadd_rn(y, bc[0]);
            const float beta = *beta_critp;
            float mem = mem_crit[i];
            float reset = (mem > 1.0f) ? 1.0f : 0.0f;
            float m = __fsub_rn(fmaf(beta, mem, y), reset);
            out[OFF_VALUE + i] = (m > 1.0f) ? 1.0f : 0.0f;
            out[OFF_MCRIT + i] = m;
        } else {
            const int j = a - 1;
            y = __fadd_rn(y, ba[j]);
            const float beta = *beta_actp;
            float mem = mem_act[(size_t)i * A_DIM + j];
            float reset = (mem > 1.0f) ? 1.0f : 0.0f;
            float m = __fsub_rn(fmaf(beta, mem, y), reset);
            out[OFF_ACTION + (size_t)i * A_DIM + j] = (m > 1.0f) ? 1.0f : 0.0f;
            out[OFF_MACT + (size_t)i * A_DIM + j] = m;
        }
    }
}

// ---------------------------------------------------------------------------
extern "C" void kernel_launch(void* const* d_in, const int* in_sizes, int n_in,
                              void* d_out, int out_size)
{
    const float* inputs   = (const float*)d_in[0];
    const float* mem1     = (const float*)d_in[1];
    const float* mem2     = (const float*)d_in[2];
    const float* mem_act  = (const float*)d_in[3];
    const float* mem_crit = (const float*)d_in[4];
    const float* W1 = (const float*)d_in[5];
    const float* b1 = (const float*)d_in[6];
    const float* W2 = (const float*)d_in[7];
    const float* b2 = (const float*)d_in[8];
    const float* Wc = (const float*)d_in[9];
    const float* bc = (const float*)d_in[10];
    const float* Wa = (const float*)d_in[11];
    const float* ba = (const float*)d_in[12];
    const float* beta1     = (const float*)d_in[13];
    const float* beta2     = (const float*)d_in[14];
    const float* beta_crit = (const float*)d_in[15];
    const float* beta_act  = (const float*)d_in[16];
    float* out = (float*)d_out;

    float *cur1, *Pp, *S2;
    unsigned* S1bits;
    cudaGetSymbolAddress((void**)&cur1, g_cur1);
    cudaGetSymbolAddress((void**)&S1bits, g_S1bits);
    cudaGetSymbolAddress((void**)&Pp, g_P);
    cudaGetSymbolAddress((void**)&S2, g_S2);

    // Allow 132 KB dynamic smem for the sparse GEMM (attribute set is
    // idempotent and not a stream op — graph-capture safe).
    static const int SMEM_BYTES = 512 * SM_STRIDE * 4;  // 135168
    cudaFuncSetAttribute(sgemm_sparse,
                         cudaFuncAttributeMaxDynamicSharedMemorySize,
                         SMEM_BYTES);

    // 1) cur1 = inputs @ W1^T + b1 (bit-exact chain)
    sgemm_nt<<<dim3(H_DIM / 128, MROWS / 128), 256>>>(
        inputs, W1, b1, cur1, MROWS, H_DIM, S_DIM);

    // 2) m1 scan -> spike bits + m1 final
    k_scan1<<<(unsigned)((NELEM + 255) / 256), 256>>>(
        cur1, mem1, beta1, out + OFF_M1, S1bits);

    // 3) sparse big GEMM: slice partials P_s (sliced1x4 chains, spiking k only)
    sgemm_sparse<<<dim3(H_DIM / 64, MBIG / 512, 4), 512, SMEM_BYTES>>>(
        S1bits, W2, Pp);

    // 4) m2 scan with fused slice merge + bias -> m2 final, S2 spikes
    k_scan2<<<(unsigned)((NELEM + 255) / 256), 256>>>(
        Pp, b2, mem2, beta2, out + OFF_M2, S2);

    // 5) heads
    k_heads<<<MROWS, 256>>>(S2, Wc, bc, Wa, ba, mem_act, mem_crit,
                            beta_crit, beta_act, out);
}

// round 10
// speedup vs baseline: 1.8580x; 1.4804x over previous
#include <cuda_runtime.h>
#include <cstddef>

// Problem dims
#define T_STEPS 16
#define B_DIM   64
#define S_DIM   512
#define H_DIM   2048
#define A_DIM   32
#define MROWS   (T_STEPS * B_DIM)          // 1024
#define NELEM   ((size_t)MROWS * H_DIM)    // 2,097,152
#define MBIG    (T_STEPS * MROWS)          // 16384
#define KWORDS  (H_DIM / 32)               // 64 bit-words per S1 row
#define PSTRIDE ((size_t)MBIG * H_DIM)     // one slice-partial plane
#define LISTCAP 520                        // per-(row,slice) index capacity (u32)
#define SM_STRIDE 66                       // 64 + 2 pad floats per k-row
#define ZOFF  (512u * SM_STRIDE * 4u)      // byte offset of the zero pad row

// Output layout: concat of (value, action, m1, m2, m_act, m_crit), fp32
#define OFF_VALUE  0
#define OFF_ACTION 1024
#define OFF_M1     33792
#define OFF_M2     2130944
#define OFF_MACT   4228096
#define OFF_MCRIT  4260864

// Scratch (device globals: allocation-free per harness rules)
__device__ float    g_cur1[MROWS * H_DIM];                 // 8 MB
__device__ unsigned g_S1bits[(size_t)MBIG * KWORDS];       // 4 MB spike bits
__device__ unsigned g_idx[(size_t)MBIG * 4 * LISTCAP];     // 136 MB index lists
__device__ unsigned g_cnt[(size_t)MBIG * 4];               // padded counts
__device__ float    g_P[(size_t)4 * MBIG * H_DIM];         // 512 MB slice partials
__device__ float    g_S2[MROWS * H_DIM];                   // 8 MB

// ---------------------------------------------------------------------------
// Packed f32x2 helpers
// ---------------------------------------------------------------------------
__device__ __forceinline__ unsigned long long pack2(float x, float y) {
    unsigned long long r;
    asm("mov.b64 %0, {%1, %2};" : "=l"(r) : "f"(x), "f"(y));
    return r;
}
__device__ __forceinline__ void fma2(unsigned long long& acc,
                                     unsigned long long a,
                                     unsigned long long b) {
    asm("fma.rn.f32x2 %0, %1, %2, %0;" : "+l"(acc) : "l"(a), "l"(b));
}
__device__ __forceinline__ void add2(unsigned long long& a,
                                     unsigned long long b) {
    asm("add.rn.f32x2 %0, %0, %1;" : "+l"(a) : "l"(b));
}
__device__ __forceinline__ float2 unpack2(unsigned long long v) {
    float2 f;
    asm("mov.b64 {%0, %1}, %2;" : "=f"(f.x), "=f"(f.y) : "l"(v));
    return f;
}

// ---------------------------------------------------------------------------
// NT SGEMM for cur1 — BIT-EXACT chain (m1=0 proven rounds 3-9). Unchanged.
// ---------------------------------------------------------------------------
__global__ __launch_bounds__(256) void sgemm_nt(
    const float* __restrict__ A, const float* __restrict__ B,
    const float* __restrict__ bias, float* __restrict__ C,
    int M, int N, int K)
{
    __shared__ float As[8][128];
    __shared__ float Bs[8][128];

    const int tid = threadIdx.x;
    const int bm = blockIdx.y * 128;
    const int bn = blockIdx.x * 128;

    const int lrow = tid >> 1;
    const int lcol = (tid & 1) * 4;

    const int tx = tid & 15;
    const int ty = tid >> 4;

    unsigned long long acc[8][4];
#pragma unroll
    for (int i = 0; i < 8; i++)
#pragma unroll
        for (int j = 0; j < 4; j++) acc[i][j] = 0ULL;

    const float* Aptr = A + (size_t)(bm + lrow) * K + lcol;
    const float* Bptr = B + (size_t)(bn + lrow) * K + lcol;

    for (int k0 = 0; k0 < K; k0 += 8) {
        float4 a4 = *(const float4*)(Aptr + k0);
        float4 b4 = *(const float4*)(Bptr + k0);
        As[lcol + 0][lrow] = a4.x; As[lcol + 1][lrow] = a4.y;
        As[lcol + 2][lrow] = a4.z; As[lcol + 3][lrow] = a4.w;
        Bs[lcol + 0][lrow] = b4.x; Bs[lcol + 1][lrow] = b4.y;
        Bs[lcol + 2][lrow] = b4.z; Bs[lcol + 3][lrow] = b4.w;
        __syncthreads();

#pragma unroll
        for (int k = 0; k < 8; k++) {
            float ar[8];
            float4 t;
            t = *(const float4*)&As[k][ty * 8];     ar[0]=t.x; ar[1]=t.y; ar[2]=t.z; ar[3]=t.w;
            t = *(const float4*)&As[k][ty * 8 + 4]; ar[4]=t.x; ar[5]=t.y; ar[6]=t.z; ar[7]=t.w;
            float4 b0 = *(const float4*)&Bs[k][tx * 8];
            float4 b1 = *(const float4*)&Bs[k][tx * 8 + 4];
            unsigned long long bp[4];
            bp[0] = pack2(b0.x, b0.y); bp[1] = pack2(b0.z, b0.w);
            bp[2] = pack2(b1.x, b1.y); bp[3] = pack2(b1.z, b1.w);
#pragma unroll
            for (int i = 0; i < 8; i++) {
                unsigned long long ap = pack2(ar[i], ar[i]);
#pragma unroll
                for (int j = 0; j < 4; j++)
                    fma2(acc[i][j], ap, bp[j]);
            }
        }
        __syncthreads();
    }

    const int row0 = bm + ty * 8;
    const int col0 = bn + tx * 8;
#pragma unroll
    for (int i = 0; i < 8; i++) {
#pragma unroll
        for (int jv = 0; jv < 2; jv++) {
            float2 p0 = unpack2(acc[i][jv * 2 + 0]);
            float2 p1 = unpack2(acc[i][jv * 2 + 1]);
            float4 v;
            v.x = __fadd_rn(p0.x, bias[col0 + jv * 4 + 0]);
            v.y = __fadd_rn(p0.y, bias[col0 + jv * 4 + 1]);
            v.z = __fadd_rn(p1.x, bias[col0 + jv * 4 + 2]);
            v.w = __fadd_rn(p1.y, bias[col0 + jv * 4 + 3]);
            *(float4*)(C + (size_t)(row0 + i) * N + col0 + jv * 4) = v;
        }
    }
}

// ---------------------------------------------------------------------------
// m1 scan (BIT-EXACT chain) — emits spike bits via ballot. Unchanged.
// ---------------------------------------------------------------------------
__global__ void k_scan1(const float* __restrict__ cur1,
                        const float* __restrict__ mem1,
                        const float* __restrict__ beta1p,
                        float* __restrict__ m1_out,
                        unsigned* __restrict__ S1bits)
{
    size_t e = (size_t)blockIdx.x * blockDim.x + threadIdx.x;
    if (e >= NELEM) return;
    const int lane = threadIdx.x & 31;
    const size_t row = e / H_DIM;
    const size_t wcol = (e % H_DIM) >> 5;
    const float beta = *beta1p;
    const float c = cur1[e];
    float m = mem1[e];
#pragma unroll
    for (int k = 0; k < T_STEPS; k++) {
        float reset = (m > 1.0f) ? 1.0f : 0.0f;
        m = __fsub_rn(fmaf(beta, m, c), reset);
        unsigned w = __ballot_sync(0xFFFFFFFFu, m > 1.0f);
        if (lane == 0)
            S1bits[((size_t)k * MROWS + row) * KWORDS + wcol] = w;
    }
    m1_out[e] = m;
}

// ---------------------------------------------------------------------------
// Index prepass: per (m-row, slice) emit ASCENDING pre-multiplied smem byte
// offsets (k_local * SM_STRIDE * 4) of spiking k, padded to a multiple of 4
// with ZOFF (zero row -> +0.0 adds, bit-neutral). One warp per (m, slice).
// ---------------------------------------------------------------------------
__global__ __launch_bounds__(256) void k_index(
    const unsigned* __restrict__ S1bits,
    unsigned* __restrict__ idx, unsigned* __restrict__ cnt)
{
    const int warp = (blockIdx.x * blockDim.x + threadIdx.x) >> 5;
    const int lane = threadIdx.x & 31;
    if (warp >= MBIG * 4) return;
    const int m = warp >> 2;
    const int s = warp & 3;

    unsigned w = 0;
    if (lane < 16)
        w = S1bits[(size_t)m * KWORDS + s * 16 + lane];
    int c = __popc(w);

    // inclusive scan over 32 lanes (lanes >=16 contribute 0)
    int incl = c;
#pragma unroll
    for (int o = 1; o < 32; o <<= 1) {
        int v = __shfl_up_sync(0xFFFFFFFFu, incl, o);
        if (lane >= o) incl += v;
    }
    int excl = incl - c;
    int total = __shfl_sync(0xFFFFFFFFu, incl, 31);
    int tot4 = (total + 3) & ~3;

    unsigned* base = idx + (size_t)warp * LISTCAP;
    int pos = excl;
    while (w) {
        int b = __ffs(w) - 1;
        w &= w - 1;
        base[pos++] = (unsigned)(lane * 32 + b) * (SM_STRIDE * 4);
    }
    if (lane == 0) {
        for (int p = total; p < tot4; p++) base[p] = ZOFF;
        cnt[warp] = (unsigned)tot4;
    }
}

// ---------------------------------------------------------------------------
// SPARSE big GEMM v2: P_s[m, n0..n0+63] via index lists.
// Per warp: one m-row; lane owns n-pair (2*lane, 2*lane+1); ascending-offset
// chain of FADD2 == the PROVEN sliced1x4 per-slice chain (zeros skipped /
// +0.0 pads are bit-neutral). Offsets prefetched 4-at-a-time (uniform LDG).
// Tile: W2[n0..n0+63][slice] at sm[k*66 + n], plus a zero row at k=512.
// ---------------------------------------------------------------------------
__global__ __launch_bounds__(512) void sgemm_sparse(
    const float* __restrict__ W2,
    const unsigned* __restrict__ idx, const unsigned* __restrict__ cnt,
    float* __restrict__ P)
{
    extern __shared__ float sm[];        // [513][SM_STRIDE]
    const int tid  = threadIdx.x;
    const int lane = tid & 31;
    const int warp = tid >> 5;
    const int n0    = blockIdx.x * 64;
    const int mbase = blockIdx.y * 2048;
    const int s     = blockIdx.z;
    const int ks    = s * 512;

    // Load W2[n0..n0+63][ks..ks+511]: sm[k*SM_STRIDE + r] = W2[n0+r][ks+k]
    for (int i = tid; i < 64 * 512; i += 512) {
        int r = i >> 9;
        int k = i & 511;
        sm[k * SM_STRIDE + r] = W2[(size_t)(n0 + r) * H_DIM + ks + k];
    }
    if (tid < SM_STRIDE) sm[512 * SM_STRIDE + tid] = 0.0f;   // zero pad row
    __syncthreads();

    const char* smB = (const char*)sm + 8 * lane;   // lane's n-pair column
    float* Pcol = P + (size_t)s * PSTRIDE + n0 + 2 * lane;

    for (int i = warp; i < 2048; i += 16) {
        const int m = mbase + i;
        const int row4 = m * 4 + s;
        const int c = (int)cnt[row4];
        const uint4* lp = (const uint4*)(idx + (size_t)row4 * LISTCAP);

        unsigned long long acc = 0ULL;
        uint4 cur = lp[0];
        for (int j = 0; j < c; j += 4) {
            uint4 nxt = lp[(j >> 2) + 1];
            add2(acc, *(const unsigned long long*)(smB + cur.x));
            add2(acc, *(const unsigned long long*)(smB + cur.y));
            add2(acc, *(const unsigned long long*)(smB + cur.z));
            add2(acc, *(const unsigned long long*)(smB + cur.w));
            cur = nxt;
        }
        float2 r = unpack2(acc);
        *(float2*)(Pcol + (size_t)m * H_DIM) = r;
    }
}

// ---------------------------------------------------------------------------
// m2 scan with fused slice merge: h = (((P0+P1)+P2)+P3) + b2, then the
// proven FMA-form leaky chain. Unchanged from round 9 (measured correct).
// ---------------------------------------------------------------------------
__global__ void k_scan2(const float* __restrict__ P,
                        const float* __restrict__ b2,
                        const float* __restrict__ mem2,
                        const float* __restrict__ beta2p,
                        float* __restrict__ m2_out,
                        float* __restrict__ S2)
{
    size_t e = (size_t)blockIdx.x * blockDim.x + threadIdx.x;
    if (e >= NELEM) return;
    const float beta = *beta2p;
    const float bias = b2[e & (H_DIM - 1)];
    float m = mem2[e];
#pragma unroll
    for (int k = 0; k < T_STEPS; k++) {
        size_t o = (size_t)k * NELEM + e;
        float h = __fadd_rn(P[o], P[PSTRIDE + o]);
        h = __fadd_rn(h, P[2 * PSTRIDE + o]);
        h = __fadd_rn(h, P[3 * PSTRIDE + o]);
        h = __fadd_rn(h, bias);
        float reset = (m > 1.0f) ? 1.0f : 0.0f;
        m = __fsub_rn(fmaf(beta, m, h), reset);
    }
    m2_out[e] = m;
    S2[e] = (m > 1.0f) ? 1.0f : 0.0f;
}

// ---------------------------------------------------------------------------
// Heads: value/action + leaky epilogues (FMA form). One block per row.
// ---------------------------------------------------------------------------
__global__ __launch_bounds__(256) void k_heads(
    const float* __restrict__ S2,
    const float* __restrict__ Wc, const float* __restrict__ bc,
    const float* __restrict__ Wa, const float* __restrict__ ba,
    const float* __restrict__ mem_act, const float* __restrict__ mem_crit,
    const float* __restrict__ beta_critp, const float* __restrict__ beta_actp,
    float* __restrict__ out)
{
    const int i = blockIdx.x;
    __shared__ float row[H_DIM];
    for (int h = threadIdx.x; h < H_DIM; h += blockDim.x)
        row[h] = S2[(size_t)i * H_DIM + h];
    __syncthreads();

    float acc[33];
#pragma unroll
    for (int a = 0; a < 33; a++) acc[a] = 0.0f;

    for (int h = threadIdx.x; h < H_DIM; h += blockDim.x) {
        float s = row[h];
        if (s != 0.0f) {
            acc[0] += Wc[h];
#pragma unroll
            for (int a = 0; a < 32; a++)
                acc[a + 1] += Wa[(size_t)a * H_DIM + h];
        }
    }

#pragma unroll
    for (int a = 0; a < 33; a++)
#pragma unroll
        for (int off = 16; off > 0; off >>= 1)
            acc[a] += __shfl_xor_sync(0xFFFFFFFFu, acc[a], off);

    __shared__ float part[8][33];
    const int wid = threadIdx.x >> 5, lane = threadIdx.x & 31;
    if (lane == 0) {
#pragma unroll
        for (int a = 0; a < 33; a++) part[wid][a] = acc[a];
    }
    __syncthreads();

    if (threadIdx.x < 33) {
        const int a = threadIdx.x;
        float y = 0.0f;
#pragma unroll
        for (int w = 0; w < 8; w++) y += part[w][a];
        if (a == 0) {
            y = __fadd_rn(y, bc[0]);
            const float beta = *beta_critp;
            float mem = mem_crit[i];
            float reset = (mem > 1.0f) ? 1.0f : 0.0f;
            float m = __fsub_rn(fmaf(beta, mem, y), reset);
            out[OFF_VALUE + i] = (m > 1.0f) ? 1.0f : 0.0f;
            out[OFF_MCRIT + i] = m;
        } else {
            const int j = a - 1;
            y = __fadd_rn(y, ba[j]);
            const float beta = *beta_actp;
            float mem = mem_act[(size_t)i * A_DIM + j];
            float reset = (mem > 1.0f) ? 1.0f : 0.0f;
            float m = __fsub_rn(fmaf(beta, mem, y), reset);
            out[OFF_ACTION + (size_t)i * A_DIM + j] = (m > 1.0f) ? 1.0f : 0.0f;
            out[OFF_MACT + (size_t)i * A_DIM + j] = m;
        }
    }
}

// ---------------------------------------------------------------------------
extern "C" void kernel_launch(void* const* d_in, const int* in_sizes, int n_in,
                              void* d_out, int out_size)
{
    const float* inputs   = (const float*)d_in[0];
    const float* mem1     = (const float*)d_in[1];
    const float* mem2     = (const float*)d_in[2];
    const float* mem_act  = (const float*)d_in[3];
    const float* mem_crit = (const float*)d_in[4];
    const float* W1 = (const float*)d_in[5];
    const float* b1 = (const float*)d_in[6];
    const float* W2 = (const float*)d_in[7];
    const float* b2 = (const float*)d_in[8];
    const float* Wc = (const float*)d_in[9];
    const float* bc = (const float*)d_in[10];
    const float* Wa = (const float*)d_in[11];
    const float* ba = (const float*)d_in[12];
    const float* beta1     = (const float*)d_in[13];
    const float* beta2     = (const float*)d_in[14];
    const float* beta_crit = (const float*)d_in[15];
    const float* beta_act  = (const float*)d_in[16];
    float* out = (float*)d_out;

    float *cur1, *Pp, *S2;
    unsigned *S1bits, *idx, *cnt;
    cudaGetSymbolAddress((void**)&cur1, g_cur1);
    cudaGetSymbolAddress((void**)&S1bits, g_S1bits);
    cudaGetSymbolAddress((void**)&idx, g_idx);
    cudaGetSymbolAddress((void**)&cnt, g_cnt);
    cudaGetSymbolAddress((void**)&Pp, g_P);
    cudaGetSymbolAddress((void**)&S2, g_S2);

    static const int SMEM_BYTES = 513 * SM_STRIDE * 4;  // 135432
    cudaFuncSetAttribute(sgemm_sparse,
                         cudaFuncAttributeMaxDynamicSharedMemorySize,
                         SMEM_BYTES);

    // 1) cur1 = inputs @ W1^T + b1 (bit-exact chain)
    sgemm_nt<<<dim3(H_DIM / 128, MROWS / 128), 256>>>(
        inputs, W1, b1, cur1, MROWS, H_DIM, S_DIM);

    // 2) m1 scan -> spike bits + m1 final
    k_scan1<<<(unsigned)((NELEM + 255) / 256), 256>>>(
        cur1, mem1, beta1, out + OFF_M1, S1bits);

    // 3) index prepass: ascending spike-offset lists per (row, slice)
    k_index<<<(MBIG * 4) / 8, 256>>>(S1bits, idx, cnt);

    // 4) sparse big GEMM v2: slice partials via branch-free indexed adds
    sgemm_sparse<<<dim3(H_DIM / 64, MBIG / 2048, 4), 512, SMEM_BYTES>>>(
        W2, idx, cnt, Pp);

    // 5) m2 scan with fused slice merge + bias -> m2 final, S2 spikes
    k_scan2<<<(unsigned)((NELEM + 255) / 256), 256>>>(
        Pp, b2, mem2, beta2, out + OFF_M2, S2);

    // 6) heads
    k_heads<<<MROWS, 256>>>(S2, Wc, bc, Wa, ba, mem_act, mem_crit,
                            beta_crit, beta_act, out);
}

// round 11
// speedup vs baseline: 2.5742x; 1.3855x over previous
#include <cuda_runtime.h>
#include <cstddef>

// Problem dims
#define T_STEPS 16
#define B_DIM   64
#define S_DIM   512
#define H_DIM   2048
#define A_DIM   32
#define MROWS   (T_STEPS * B_DIM)          // 1024 (tb rows)
#define NELEM   ((size_t)MROWS * H_DIM)    // 2,097,152
#define MBIG    (T_STEPS * MROWS)          // 16384
#define KWORDS  (H_DIM / 32)               // 64 bit-words per S1 row
#define PSTRIDE ((size_t)MBIG * H_DIM)     // one slice-partial plane
#define ENTCAP  520                        // per-(tb,slice) union entries (u64)
#define SM_STRIDE 66                       // 64 + 2 pad floats per k-row
#define ZOFF  (512u * SM_STRIDE * 4u)      // byte offset of the zero pad row

// Output layout: concat of (value, action, m1, m2, m_act, m_crit), fp32
#define OFF_VALUE  0
#define OFF_ACTION 1024
#define OFF_M1     33792
#define OFF_M2     2130944
#define OFF_MACT   4228096
#define OFF_MCRIT  4260864

// Scratch (device globals: allocation-free per harness rules)
__device__ float    g_cur1[MROWS * H_DIM];                  // 8 MB
__device__ unsigned g_S1bits[(size_t)MBIG * KWORDS];        // 4 MB spike bits
__device__ unsigned long long g_ent[(size_t)MROWS * 4 * ENTCAP]; // 17 MB union lists
__device__ unsigned g_cnt[MROWS * 4];                       // padded union counts
__device__ float    g_P[(size_t)4 * MBIG * H_DIM];          // 512 MB slice partials
__device__ float    g_S2[MROWS * H_DIM];                    // 8 MB

// ---------------------------------------------------------------------------
// Packed f32x2 helpers
// ---------------------------------------------------------------------------
__device__ __forceinline__ unsigned long long pack2(float x, float y) {
    unsigned long long r;
    asm("mov.b64 %0, {%1, %2};" : "=l"(r) : "f"(x), "f"(y));
    return r;
}
__device__ __forceinline__ void fma2(unsigned long long& acc,
                                     unsigned long long a,
                                     unsigned long long b) {
    asm("fma.rn.f32x2 %0, %1, %2, %0;" : "+l"(acc) : "l"(a), "l"(b));
}
__device__ __forceinline__ float2 unpack2(unsigned long long v) {
    float2 f;
    asm("mov.b64 {%0, %1}, %2;" : "=f"(f.x), "=f"(f.y) : "l"(v));
    return f;
}
// Explicitly predicated packed add (round-8 pattern, proven bit-neutral skip):
// if (m != 0) acc += w  (two fp32 lanes, rn each)
__device__ __forceinline__ void padd2(unsigned long long& acc,
                                      unsigned m, unsigned long long w) {
    asm("{\n\t"
        ".reg .pred p;\n\t"
        "setp.ne.u32 p, %1, 0;\n\t"
        "@p add.rn.f32x2 %0, %0, %2;\n\t"
        "}"
        : "+l"(acc) : "r"(m), "l"(w));
}

// ---------------------------------------------------------------------------
// NT SGEMM for cur1 — BIT-EXACT chain (m1=0 proven rounds 3-10). Unchanged.
// ---------------------------------------------------------------------------
__global__ __launch_bounds__(256) void sgemm_nt(
    const float* __restrict__ A, const float* __restrict__ B,
    const float* __restrict__ bias, float* __restrict__ C,
    int M, int N, int K)
{
    __shared__ float As[8][128];
    __shared__ float Bs[8][128];

    const int tid = threadIdx.x;
    const int bm = blockIdx.y * 128;
    const int bn = blockIdx.x * 128;

    const int lrow = tid >> 1;
    const int lcol = (tid & 1) * 4;

    const int tx = tid & 15;
    const int ty = tid >> 4;

    unsigned long long acc[8][4];
#pragma unroll
    for (int i = 0; i < 8; i++)
#pragma unroll
        for (int j = 0; j < 4; j++) acc[i][j] = 0ULL;

    const float* Aptr = A + (size_t)(bm + lrow) * K + lcol;
    const float* Bptr = B + (size_t)(bn + lrow) * K + lcol;

    for (int k0 = 0; k0 < K; k0 += 8) {
        float4 a4 = *(const float4*)(Aptr + k0);
        float4 b4 = *(const float4*)(Bptr + k0);
        As[lcol + 0][lrow] = a4.x; As[lcol + 1][lrow] = a4.y;
        As[lcol + 2][lrow] = a4.z; As[lcol + 3][lrow] = a4.w;
        Bs[lcol + 0][lrow] = b4.x; Bs[lcol + 1][lrow] = b4.y;
        Bs[lcol + 2][lrow] = b4.z; Bs[lcol + 3][lrow] = b4.w;
        __syncthreads();

#pragma unroll
        for (int k = 0; k < 8; k++) {
            float ar[8];
            float4 t;
            t = *(const float4*)&As[k][ty * 8];     ar[0]=t.x; ar[1]=t.y; ar[2]=t.z; ar[3]=t.w;
            t = *(const float4*)&As[k][ty * 8 + 4]; ar[4]=t.x; ar[5]=t.y; ar[6]=t.z; ar[7]=t.w;
            float4 b0 = *(const float4*)&Bs[k][tx * 8];
            float4 b1 = *(const float4*)&Bs[k][tx * 8 + 4];
            unsigned long long bp[4];
            bp[0] = pack2(b0.x, b0.y); bp[1] = pack2(b0.z, b0.w);
            bp[2] = pack2(b1.x, b1.y); bp[3] = pack2(b1.z, b1.w);
#pragma unroll
            for (int i = 0; i < 8; i++) {
                unsigned long long ap = pack2(ar[i], ar[i]);
#pragma unroll
                for (int j = 0; j < 4; j++)
                    fma2(acc[i][j], ap, bp[j]);
            }
        }
        __syncthreads();
    }

    const int row0 = bm + ty * 8;
    const int col0 = bn + tx * 8;
#pragma unroll
    for (int i = 0; i < 8; i++) {
#pragma unroll
        for (int jv = 0; jv < 2; jv++) {
            float2 p0 = unpack2(acc[i][jv * 2 + 0]);
            float2 p1 = unpack2(acc[i][jv * 2 + 1]);
            float4 v;
            v.x = __fadd_rn(p0.x, bias[col0 + jv * 4 + 0]);
            v.y = __fadd_rn(p0.y, bias[col0 + jv * 4 + 1]);
            v.z = __fadd_rn(p1.x, bias[col0 + jv * 4 + 2]);
            v.w = __fadd_rn(p1.y, bias[col0 + jv * 4 + 3]);
            *(float4*)(C + (size_t)(row0 + i) * N + col0 + jv * 4) = v;
        }
    }
}

// ---------------------------------------------------------------------------
// m1 scan (BIT-EXACT chain) — emits spike bits via ballot. Unchanged.
// ---------------------------------------------------------------------------
__global__ void k_scan1(const float* __restrict__ cur1,
                        const float* __restrict__ mem1,
                        const float* __restrict__ beta1p,
                        float* __restrict__ m1_out,
                        unsigned* __restrict__ S1bits)
{
    size_t e = (size_t)blockIdx.x * blockDim.x + threadIdx.x;
    if (e >= NELEM) return;
    const int lane = threadIdx.x & 31;
    const size_t row = e / H_DIM;
    const size_t wcol = (e % H_DIM) >> 5;
    const float beta = *beta1p;
    const float c = cur1[e];
    float m = mem1[e];
#pragma unroll
    for (int k = 0; k < T_STEPS; k++) {
        float reset = (m > 1.0f) ? 1.0f : 0.0f;
        m = __fsub_rn(fmaf(beta, m, c), reset);
        unsigned w = __ballot_sync(0xFFFFFFFFu, m > 1.0f);
        if (lane == 0)
            S1bits[((size_t)k * MROWS + row) * KWORDS + wcol] = w;
    }
    m1_out[e] = m;
}

// ---------------------------------------------------------------------------
// Index prepass v2: per (tb, slice) build the UNION spike list over all 16
// steps: u64 entries {lo32 = k_local*SM_STRIDE*4 byte offset, hi32 = 16-bit
// step-membership mask}, ascending k, padded to even count with {ZOFF, 0}.
// One warp per (tb, slice); lane l<16 owns k-word l of the slice.
// ---------------------------------------------------------------------------
__global__ __launch_bounds__(256) void k_index(
    const unsigned* __restrict__ S1bits,
    unsigned long long* __restrict__ ent, unsigned* __restrict__ cnt)
{
    const int task = (blockIdx.x * blockDim.x + threadIdx.x) >> 5;
    const int lane = threadIdx.x & 31;
    if (task >= MROWS * 4) return;
    const int tb = task >> 2;
    const int s  = task & 3;

    unsigned w16[T_STEPS];
    unsigned uni = 0;
#pragma unroll
    for (int st = 0; st < T_STEPS; st++) {
        unsigned w = 0;
        if (lane < 16)
            w = S1bits[((size_t)st * MROWS + tb) * KWORDS + s * 16 + lane];
        w16[st] = w;
        uni |= w;
    }
    int c = __popc(uni);

    // exclusive scan of counts over lanes
    int incl = c;
#pragma unroll
    for (int o = 1; o < 32; o <<= 1) {
        int v = __shfl_up_sync(0xFFFFFFFFu, incl, o);
        if (lane >= o) incl += v;
    }
    int excl = incl - c;
    int total = __shfl_sync(0xFFFFFFFFu, incl, 31);
    int tot2 = (total + 1) & ~1;

    unsigned long long* base = ent + (size_t)task * ENTCAP;
    int pos = excl;
    unsigned u = uni;
    while (u) {
        int b = __ffs(u) - 1;
        u &= u - 1;
        unsigned mask = 0;
#pragma unroll
        for (int st = 0; st < T_STEPS; st++)
            mask |= ((w16[st] >> b) & 1u) << st;
        unsigned off = (unsigned)(lane * 32 + b) * (SM_STRIDE * 4);
        base[pos++] = ((unsigned long long)mask << 32) | off;
    }
    if (lane == 0) {
        for (int p = total; p < tot2; p++)
            base[p] = (unsigned long long)ZOFF;   // mask=0 pad
        cnt[task] = (unsigned)tot2;
    }
}

// ---------------------------------------------------------------------------
// SPARSE big GEMM v3: one warp computes ALL 16 step-partials of one
// (tb, slice, 64-n block). Per union-k: ONE LDS.64 of the n-pair operand,
// then predicated add into the member steps' accumulators (ascending k ->
// each step's chain is the PROVEN sliced1x4 per-slice chain; skipped /
// pad adds are bit-neutral). W2 slice tile in 132KB smem + zero row.
// Grid (32 nblk, 8 tb-groups, 4 slices), 512 threads (16 warps).
// ---------------------------------------------------------------------------
__global__ __launch_bounds__(512) void sgemm_sparse(
    const float* __restrict__ W2,
    const unsigned long long* __restrict__ ent, const unsigned* __restrict__ cnt,
    float* __restrict__ P)
{
    extern __shared__ float sm[];        // [513][SM_STRIDE]
    const int tid  = threadIdx.x;
    const int lane = tid & 31;
    const int warp = tid >> 5;
    const int n0    = blockIdx.x * 64;
    const int tbb   = blockIdx.y * 128;
    const int s     = blockIdx.z;
    const int ks    = s * 512;

    // Load W2[n0..n0+63][ks..ks+511]: sm[k*SM_STRIDE + r] = W2[n0+r][ks+k]
    for (int i = tid; i < 64 * 512; i += 512) {
        int r = i >> 9;
        int k = i & 511;
        sm[k * SM_STRIDE + r] = W2[(size_t)(n0 + r) * H_DIM + ks + k];
    }
    if (tid < SM_STRIDE) sm[512 * SM_STRIDE + tid] = 0.0f;   // zero pad row
    __syncthreads();

    const char* smB = (const char*)sm + 8 * lane;   // lane's n-pair column
    float* Pbase = P + (size_t)s * PSTRIDE + n0 + 2 * lane;

    for (int i = warp; i < 128; i += 16) {
        const int tb = tbb + i;
        const int task = tb * 4 + s;
        const int U2 = (int)cnt[task];
        const uint4* lp = (const uint4*)(ent + (size_t)task * ENTCAP);

        unsigned long long acc[T_STEPS];
#pragma unroll
        for (int st = 0; st < T_STEPS; st++) acc[st] = 0ULL;

        uint4 cur = lp[0];
        for (int j = 0; j < U2; j += 2) {
            uint4 nxt = lp[(j >> 1) + 1];
            unsigned long long w0 = *(const unsigned long long*)(smB + cur.x);
            unsigned m0 = cur.y;
#pragma unroll
            for (int st = 0; st < T_STEPS; st++)
                padd2(acc[st], m0 & (1u << st), w0);
            unsigned long long w1 = *(const unsigned long long*)(smB + cur.z);
            unsigned m1 = cur.w;
#pragma unroll
            for (int st = 0; st < T_STEPS; st++)
                padd2(acc[st], m1 & (1u << st), w1);
            cur = nxt;
        }

#pragma unroll
        for (int st = 0; st < T_STEPS; st++) {
            float2 r = unpack2(acc[st]);
            *(float2*)(Pbase + ((size_t)st * MROWS + tb) * H_DIM) = r;
        }
    }
}

// ---------------------------------------------------------------------------
// m2 scan with fused slice merge: h = (((P0+P1)+P2)+P3) + b2, then the
// proven FMA-form leaky chain. Unchanged (measured correct rounds 9-10).
// ---------------------------------------------------------------------------
__global__ void k_scan2(const float* __restrict__ P,
                        const float* __restrict__ b2,
                        const float* __restrict__ mem2,
                        const float* __restrict__ beta2p,
                        float* __restrict__ m2_out,
                        float* __restrict__ S2)
{
    size_t e = (size_t)blockIdx.x * blockDim.x + threadIdx.x;
    if (e >= NELEM) return;
    const float beta = *beta2p;
    const float bias = b2[e & (H_DIM - 1)];
    float m = mem2[e];
#pragma unroll
    for (int k = 0; k < T_STEPS; k++) {
        size_t o = (size_t)k * NELEM + e;
        float h = __fadd_rn(P[o], P[PSTRIDE + o]);
        h = __fadd_rn(h, P[2 * PSTRIDE + o]);
        h = __fadd_rn(h, P[3 * PSTRIDE + o]);
        h = __fadd_rn(h, bias);
        float reset = (m > 1.0f) ? 1.0f : 0.0f;
        m = __fsub_rn(fmaf(beta, m, h), reset);
    }
    m2_out[e] = m;
    S2[e] = (m > 1.0f) ? 1.0f : 0.0f;
}

// ---------------------------------------------------------------------------
// Heads: value/action + leaky epilogues (FMA form). One block per row.
// ---------------------------------------------------------------------------
__global__ __launch_bounds__(256) void k_heads(
    const float* __restrict__ S2,
    const float* __restrict__ Wc, const float* __restrict__ bc,
    const float* __restrict__ Wa, const float* __restrict__ ba,
    const float* __restrict__ mem_act, const float* __restrict__ mem_crit,
    const float* __restrict__ beta_critp, const float* __restrict__ beta_actp,
    float* __restrict__ out)
{
    const int i = blockIdx.x;
    __shared__ float row[H_DIM];
    for (int h = threadIdx.x; h < H_DIM; h += blockDim.x)
        row[h] = S2[(size_t)i * H_DIM + h];
    __syncthreads();

    float acc[33];
#pragma unroll
    for (int a = 0; a < 33; a++) acc[a] = 0.0f;

    for (int h = threadIdx.x; h < H_DIM; h += blockDim.x) {
        float s = row[h];
        if (s != 0.0f) {
            acc[0] += Wc[h];
#pragma unroll
            for (int a = 0; a < 32; a++)
                acc[a + 1] += Wa[(size_t)a * H_DIM + h];
        }
    }

#pragma unroll
    for (int a = 0; a < 33; a++)
#pragma unroll
        for (int off = 16; off > 0; off >>= 1)
            acc[a] += __shfl_xor_sync(0xFFFFFFFFu, acc[a], off);

    __shared__ float part[8][33];
    const int wid = threadIdx.x >> 5, lane = threadIdx.x & 31;
    if (lane == 0) {
#pragma unroll
        for (int a = 0; a < 33; a++) part[wid][a] = acc[a];
    }
    __syncthreads();

    if (threadIdx.x < 33) {
        const int a = threadIdx.x;
        float y = 0.0f;
#pragma unroll
        for (int w = 0; w < 8; w++) y += part[w][a];
        if (a == 0) {
            y = __fadd_rn(y, bc[0]);
            const float beta = *beta_critp;
            float mem = mem_crit[i];
            float reset = (mem > 1.0f) ? 1.0f : 0.0f;
            float m = __fsub_rn(fmaf(beta, mem, y), reset);
            out[OFF_VALUE + i] = (m > 1.0f) ? 1.0f : 0.0f;
            out[OFF_MCRIT + i] = m;
        } else {
            const int j = a - 1;
            y = __fadd_rn(y, ba[j]);
            const float beta = *beta_actp;
            float mem = mem_act[(size_t)i * A_DIM + j];
            float reset = (mem > 1.0f) ? 1.0f : 0.0f;
            float m = __fsub_rn(fmaf(beta, mem, y), reset);
            out[OFF_ACTION + (size_t)i * A_DIM + j] = (m > 1.0f) ? 1.0f : 0.0f;
            out[OFF_MACT + (size_t)i * A_DIM + j] = m;
        }
    }
}

// ---------------------------------------------------------------------------
extern "C" void kernel_launch(void* const* d_in, const int* in_sizes, int n_in,
                              void* d_out, int out_size)
{
    const float* inputs   = (const float*)d_in[0];
    const float* mem1     = (const float*)d_in[1];
    const float* mem2     = (const float*)d_in[2];
    const float* mem_act  = (const float*)d_in[3];
    const float* mem_crit = (const float*)d_in[4];
    const float* W1 = (const float*)d_in[5];
    const float* b1 = (const float*)d_in[6];
    const float* W2 = (const float*)d_in[7];
    const float* b2 = (const float*)d_in[8];
    const float* Wc = (const float*)d_in[9];
    const float* bc = (const float*)d_in[10];
    const float* Wa = (const float*)d_in[11];
    const float* ba = (const float*)d_in[12];
    const float* beta1     = (const float*)d_in[13];
    const float* beta2     = (const float*)d_in[14];
    const float* beta_crit = (const float*)d_in[15];
    const float* beta_act  = (const float*)d_in[16];
    float* out = (float*)d_out;

    float *cur1, *Pp, *S2;
    unsigned *S1bits, *cnt;
    unsigned long long* ent;
    cudaGetSymbolAddress((void**)&cur1, g_cur1);
    cudaGetSymbolAddress((void**)&S1bits, g_S1bits);
    cudaGetSymbolAddress((void**)&ent, g_ent);
    cudaGetSymbolAddress((void**)&cnt, g_cnt);
    cudaGetSymbolAddress((void**)&Pp, g_P);
    cudaGetSymbolAddress((void**)&S2, g_S2);

    static const int SMEM_BYTES = 513 * SM_STRIDE * 4;  // 135432
    cudaFuncSetAttribute(sgemm_sparse,
                         cudaFuncAttributeMaxDynamicSharedMemorySize,
                         SMEM_BYTES);

    // 1) cur1 = inputs @ W1^T + b1 (bit-exact chain)
    sgemm_nt<<<dim3(H_DIM / 128, MROWS / 128), 256>>>(
        inputs, W1, b1, cur1, MROWS, H_DIM, S_DIM);

    // 2) m1 scan -> spike bits + m1 final
    k_scan1<<<(unsigned)((NELEM + 255) / 256), 256>>>(
        cur1, mem1, beta1, out + OFF_M1, S1bits);

    // 3) index prepass v2: union lists with step-membership masks
    k_index<<<(MROWS * 4) / 8, 256>>>(S1bits, ent, cnt);

    // 4) sparse big GEMM v3: 16 steps per warp, one smem read per union-k
    sgemm_sparse<<<dim3(H_DIM / 64, MROWS / 128, 4), 512, SMEM_BYTES>>>(
        W2, ent, cnt, Pp);

    // 5) m2 scan with fused slice merge + bias -> m2 final, S2 spikes
    k_scan2<<<(unsigned)((NELEM + 255) / 256), 256>>>(
        Pp, b2, mem2, beta2, out + OFF_M2, S2);

    // 6) heads
    k_heads<<<MROWS, 256>>>(S2, Wc, bc, Wa, ba, mem_act, mem_crit,
                            beta_crit, beta_act, out);
}

// round 12
// speedup vs baseline: 2.5871x; 1.0050x over previous
#include <cuda_runtime.h>
#include <cstddef>

// Problem dims
#define T_STEPS 16
#define B_DIM   64
#define S_DIM   512
#define H_DIM   2048
#define A_DIM   32
#define MROWS   (T_STEPS * B_DIM)          // 1024 (tb rows)
#define NELEM   ((size_t)MROWS * H_DIM)    // 2,097,152
#define MBIG    (T_STEPS * MROWS)          // 16384
#define KWORDS  (H_DIM / 32)               // 64 bit-words per S1 row
#define PSTRIDE ((size_t)MBIG * H_DIM)     // one slice-partial plane
#define ENTCAP  520                        // per-(tb,slice) union entries (u64)
#define SM_STRIDE 66                       // 64 + 2 pad floats per k-row
#define ZOFF  (512u * SM_STRIDE * 4u)      // byte offset of the zero pad row

// Output layout: concat of (value, action, m1, m2, m_act, m_crit), fp32
#define OFF_VALUE  0
#define OFF_ACTION 1024
#define OFF_M1     33792
#define OFF_M2     2130944
#define OFF_MACT   4228096
#define OFF_MCRIT  4260864

// Scratch (device globals: allocation-free per harness rules)
__device__ float    g_cur1[MROWS * H_DIM];                  // 8 MB
__device__ unsigned g_S1bits[(size_t)MBIG * KWORDS];        // 4 MB spike bits
__device__ unsigned long long g_ent[(size_t)MROWS * 4 * ENTCAP]; // 17 MB union lists
__device__ unsigned g_cnt[MROWS * 4];                       // padded union counts
__device__ float    g_P[(size_t)4 * MBIG * H_DIM];          // 512 MB slice partials
__device__ float    g_S2[MROWS * H_DIM];                    // 8 MB

// ---------------------------------------------------------------------------
// Packed f32x2 helpers
// ---------------------------------------------------------------------------
__device__ __forceinline__ unsigned long long pack2(float x, float y) {
    unsigned long long r;
    asm("mov.b64 %0, {%1, %2};" : "=l"(r) : "f"(x), "f"(y));
    return r;
}
__device__ __forceinline__ void fma2(unsigned long long& acc,
                                     unsigned long long a,
                                     unsigned long long b) {
    asm("fma.rn.f32x2 %0, %1, %2, %0;" : "+l"(acc) : "l"(a), "l"(b));
}
__device__ __forceinline__ float2 unpack2(unsigned long long v) {
    float2 f;
    asm("mov.b64 {%0, %1}, %2;" : "=f"(f.x), "=f"(f.y) : "l"(v));
    return f;
}
// Fused bit-test + predicated packed add. and+setp adjacent in ONE asm block
// so ptxas fuses them into a single LOP3.LUT-with-predicate (1 alu op), then
// @p add.rn.f32x2 (1 fma op). Skip (bit clear) is bit-neutral (acc never -0).
__device__ __forceinline__ void bitadd2(unsigned long long& acc,
                                        unsigned mask, unsigned bit,
                                        unsigned long long w) {
    asm("{\n\t"
        ".reg .pred p;\n\t"
        ".reg .b32 t;\n\t"
        "and.b32 t, %1, %2;\n\t"
        "setp.ne.b32 p, t, 0;\n\t"
        "@p add.rn.f32x2 %0, %0, %3;\n\t"
        "}"
        : "+l"(acc) : "r"(mask), "r"(bit), "l"(w));
}

// ---------------------------------------------------------------------------
// NT SGEMM for cur1 — BIT-EXACT chain (m1=0 proven rounds 3-11). Unchanged.
// ---------------------------------------------------------------------------
__global__ __launch_bounds__(256) void sgemm_nt(
    const float* __restrict__ A, const float* __restrict__ B,
    const float* __restrict__ bias, float* __restrict__ C,
    int M, int N, int K)
{
    __shared__ float As[8][128];
    __shared__ float Bs[8][128];

    const int tid = threadIdx.x;
    const int bm = blockIdx.y * 128;
    const int bn = blockIdx.x * 128;

    const int lrow = tid >> 1;
    const int lcol = (tid & 1) * 4;

    const int tx = tid & 15;
    const int ty = tid >> 4;

    unsigned long long acc[8][4];
#pragma unroll
    for (int i = 0; i < 8; i++)
#pragma unroll
        for (int j = 0; j < 4; j++) acc[i][j] = 0ULL;

    const float* Aptr = A + (size_t)(bm + lrow) * K + lcol;
    const float* Bptr = B + (size_t)(bn + lrow) * K + lcol;

    for (int k0 = 0; k0 < K; k0 += 8) {
        float4 a4 = *(const float4*)(Aptr + k0);
        float4 b4 = *(const float4*)(Bptr + k0);
        As[lcol + 0][lrow] = a4.x; As[lcol + 1][lrow] = a4.y;
        As[lcol + 2][lrow] = a4.z; As[lcol + 3][lrow] = a4.w;
        Bs[lcol + 0][lrow] = b4.x; Bs[lcol + 1][lrow] = b4.y;
        Bs[lcol + 2][lrow] = b4.z; Bs[lcol + 3][lrow] = b4.w;
        __syncthreads();

#pragma unroll
        for (int k = 0; k < 8; k++) {
            float ar[8];
            float4 t;
            t = *(const float4*)&As[k][ty * 8];     ar[0]=t.x; ar[1]=t.y; ar[2]=t.z; ar[3]=t.w;
            t = *(const float4*)&As[k][ty * 8 + 4]; ar[4]=t.x; ar[5]=t.y; ar[6]=t.z; ar[7]=t.w;
            float4 b0 = *(const float4*)&Bs[k][tx * 8];
            float4 b1 = *(const float4*)&Bs[k][tx * 8 + 4];
            unsigned long long bp[4];
            bp[0] = pack2(b0.x, b0.y); bp[1] = pack2(b0.z, b0.w);
            bp[2] = pack2(b1.x, b1.y); bp[3] = pack2(b1.z, b1.w);
#pragma unroll
            for (int i = 0; i < 8; i++) {
                unsigned long long ap = pack2(ar[i], ar[i]);
#pragma unroll
                for (int j = 0; j < 4; j++)
                    fma2(acc[i][j], ap, bp[j]);
            }
        }
        __syncthreads();
    }

    const int row0 = bm + ty * 8;
    const int col0 = bn + tx * 8;
#pragma unroll
    for (int i = 0; i < 8; i++) {
#pragma unroll
        for (int jv = 0; jv < 2; jv++) {
            float2 p0 = unpack2(acc[i][jv * 2 + 0]);
            float2 p1 = unpack2(acc[i][jv * 2 + 1]);
            float4 v;
            v.x = __fadd_rn(p0.x, bias[col0 + jv * 4 + 0]);
            v.y = __fadd_rn(p0.y, bias[col0 + jv * 4 + 1]);
            v.z = __fadd_rn(p1.x, bias[col0 + jv * 4 + 2]);
            v.w = __fadd_rn(p1.y, bias[col0 + jv * 4 + 3]);
            *(float4*)(C + (size_t)(row0 + i) * N + col0 + jv * 4) = v;
        }
    }
}

// ---------------------------------------------------------------------------
// m1 scan (BIT-EXACT chain) — emits spike bits via ballot. Unchanged.
// ---------------------------------------------------------------------------
__global__ void k_scan1(const float* __restrict__ cur1,
                        const float* __restrict__ mem1,
                        const float* __restrict__ beta1p,
                        float* __restrict__ m1_out,
                        unsigned* __restrict__ S1bits)
{
    size_t e = (size_t)blockIdx.x * blockDim.x + threadIdx.x;
    if (e >= NELEM) return;
    const int lane = threadIdx.x & 31;
    const size_t row = e / H_DIM;
    const size_t wcol = (e % H_DIM) >> 5;
    const float beta = *beta1p;
    const float c = cur1[e];
    float m = mem1[e];
#pragma unroll
    for (int k = 0; k < T_STEPS; k++) {
        float reset = (m > 1.0f) ? 1.0f : 0.0f;
        m = __fsub_rn(fmaf(beta, m, c), reset);
        unsigned w = __ballot_sync(0xFFFFFFFFu, m > 1.0f);
        if (lane == 0)
            S1bits[((size_t)k * MROWS + row) * KWORDS + wcol] = w;
    }
    m1_out[e] = m;
}

// ---------------------------------------------------------------------------
// Index prepass v2: union spike lists with 16-bit step-membership masks,
// ascending k. Pads 8 extra ZOFF entries past `total` so the GEMM's 4-deep
// uint4 prefetch always reads initialized, bit-neutral data (max 512+8=520).
// ---------------------------------------------------------------------------
__global__ __launch_bounds__(256) void k_index(
    const unsigned* __restrict__ S1bits,
    unsigned long long* __restrict__ ent, unsigned* __restrict__ cnt)
{
    const int task = (blockIdx.x * blockDim.x + threadIdx.x) >> 5;
    const int lane = threadIdx.x & 31;
    if (task >= MROWS * 4) return;
    const int tb = task >> 2;
    const int s  = task & 3;

    unsigned w16[T_STEPS];
    unsigned uni = 0;
#pragma unroll
    for (int st = 0; st < T_STEPS; st++) {
        unsigned w = 0;
        if (lane < 16)
            w = S1bits[((size_t)st * MROWS + tb) * KWORDS + s * 16 + lane];
        w16[st] = w;
        uni |= w;
    }
    int c = __popc(uni);

    // exclusive scan of counts over lanes
    int incl = c;
#pragma unroll
    for (int o = 1; o < 32; o <<= 1) {
        int v = __shfl_up_sync(0xFFFFFFFFu, incl, o);
        if (lane >= o) incl += v;
    }
    int excl = incl - c;
    int total = __shfl_sync(0xFFFFFFFFu, incl, 31);
    int tot2 = (total + 1) & ~1;

    unsigned long long* base = ent + (size_t)task * ENTCAP;
    int pos = excl;
    unsigned u = uni;
    while (u) {
        int b = __ffs(u) - 1;
        u &= u - 1;
        unsigned mask = 0;
#pragma unroll
        for (int st = 0; st < T_STEPS; st++)
            mask |= ((w16[st] >> b) & 1u) << st;
        unsigned off = (unsigned)(lane * 32 + b) * (SM_STRIDE * 4);
        base[pos++] = ((unsigned long long)mask << 32) | off;
    }
    if (lane == 0) {
        int pend = total + 8;
        if (pend > ENTCAP) pend = ENTCAP;
        for (int p = total; p < pend; p++)
            base[p] = (unsigned long long)ZOFF;   // mask=0 pad
        cnt[task] = (unsigned)tot2;
    }
}

// ---------------------------------------------------------------------------
// SPARSE big GEMM v4: union lists, 16 step-accs per warp, fused LOP3.pred
// bit-test + predicated FADD2 (ascending k -> PROVEN sliced1x4 chain per
// step; skips/pads bit-neutral). 768 threads (24 warps) for latency hiding;
// 4-deep uint4 list prefetch covers the L2 latency of list loads.
// Grid (32 nblk, 8 tb-groups, 4 slices).
// ---------------------------------------------------------------------------
__global__ __launch_bounds__(768) void sgemm_sparse(
    const float* __restrict__ W2,
    const unsigned long long* __restrict__ ent, const unsigned* __restrict__ cnt,
    float* __restrict__ P)
{
    extern __shared__ float sm[];        // [513][SM_STRIDE]
    const int tid  = threadIdx.x;
    const int lane = tid & 31;
    const int warp = tid >> 5;
    const int n0    = blockIdx.x * 64;
    const int tbb   = blockIdx.y * 128;
    const int s     = blockIdx.z;
    const int ks    = s * 512;

    // Load W2[n0..n0+63][ks..ks+511]: sm[k*SM_STRIDE + r] = W2[n0+r][ks+k]
    for (int i = tid; i < 64 * 512; i += 768) {
        int r = i >> 9;
        int k = i & 511;
        sm[k * SM_STRIDE + r] = W2[(size_t)(n0 + r) * H_DIM + ks + k];
    }
    if (tid < SM_STRIDE) sm[512 * SM_STRIDE + tid] = 0.0f;   // zero pad row
    __syncthreads();

    const char* smB = (const char*)sm + 8 * lane;   // lane's n-pair column
    float* Pbase = P + (size_t)s * PSTRIDE + n0 + 2 * lane;

    for (int i = warp; i < 128; i += 24) {
        const int tb = tbb + i;
        const int task = tb * 4 + s;
        const int nvec = ((int)cnt[task]) >> 1;     // uint4s (2 entries each)
        const uint4* lp = (const uint4*)(ent + (size_t)task * ENTCAP);

        unsigned long long acc[T_STEPS];
#pragma unroll
        for (int st = 0; st < T_STEPS; st++) acc[st] = 0ULL;

        // 4-deep prefetch pipeline (pads guarantee initialized reads)
        uint4 q0 = lp[0], q1 = lp[1], q2 = lp[2], q3 = lp[3];
        unsigned long long w0 = *(const unsigned long long*)(smB + q0.x);
        unsigned long long w1 = *(const unsigned long long*)(smB + q0.z);

#pragma unroll 4
        for (int j = 0; j < nvec; j++) {
            uint4 qn = lp[j + 4];
            unsigned long long nw0 = *(const unsigned long long*)(smB + q1.x);
            unsigned long long nw1 = *(const unsigned long long*)(smB + q1.z);
            const unsigned m0 = q0.y, m1 = q0.w;
#pragma unroll
            for (int st = 0; st < T_STEPS; st++)
                bitadd2(acc[st], m0, 1u << st, w0);
#pragma unroll
            for (int st = 0; st < T_STEPS; st++)
                bitadd2(acc[st], m1, 1u << st, w1);
            q0 = q1; q1 = q2; q2 = q3; q3 = qn;
            w0 = nw0; w1 = nw1;
        }

#pragma unroll
        for (int st = 0; st < T_STEPS; st++) {
            float2 r = unpack2(acc[st]);
            *(float2*)(Pbase + ((size_t)st * MROWS + tb) * H_DIM) = r;
        }
    }
}

// ---------------------------------------------------------------------------
// m2 scan with fused slice merge: h = (((P0+P1)+P2)+P3) + b2, then the
// proven FMA-form leaky chain. Unchanged (measured correct rounds 9-11).
// ---------------------------------------------------------------------------
__global__ void k_scan2(const float* __restrict__ P,
                        const float* __restrict__ b2,
                        const float* __restrict__ mem2,
                        const float* __restrict__ beta2p,
                        float* __restrict__ m2_out,
                        float* __restrict__ S2)
{
    size_t e = (size_t)blockIdx.x * blockDim.x + threadIdx.x;
    if (e >= NELEM) return;
    const float beta = *beta2p;
    const float bias = b2[e & (H_DIM - 1)];
    float m = mem2[e];
#pragma unroll
    for (int k = 0; k < T_STEPS; k++) {
        size_t o = (size_t)k * NELEM + e;
        float h = __fadd_rn(P[o], P[PSTRIDE + o]);
        h = __fadd_rn(h, P[2 * PSTRIDE + o]);
        h = __fadd_rn(h, P[3 * PSTRIDE + o]);
        h = __fadd_rn(h, bias);
        float reset = (m > 1.0f) ? 1.0f : 0.0f;
        m = __fsub_rn(fmaf(beta, m, h), reset);
    }
    m2_out[e] = m;
    S2[e] = (m > 1.0f) ? 1.0f : 0.0f;
}

// ---------------------------------------------------------------------------
// Heads: value/action + leaky epilogues (FMA form). One block per row.
// ---------------------------------------------------------------------------
__global__ __launch_bounds__(256) void k_heads(
    const float* __restrict__ S2,
    const float* __restrict__ Wc, const float* __restrict__ bc,
    const float* __restrict__ Wa, const float* __restrict__ ba,
    const float* __restrict__ mem_act, const float* __restrict__ mem_crit,
    const float* __restrict__ beta_critp, const float* __restrict__ beta_actp,
    float* __restrict__ out)
{
    const int i = blockIdx.x;
    __shared__ float row[H_DIM];
    for (int h = threadIdx.x; h < H_DIM; h += blockDim.x)
        row[h] = S2[(size_t)i * H_DIM + h];
    __syncthreads();

    float acc[33];
#pragma unroll
    for (int a = 0; a < 33; a++) acc[a] = 0.0f;

    for (int h = threadIdx.x; h < H_DIM; h += blockDim.x) {
        float s = row[h];
        if (s != 0.0f) {
            acc[0] += Wc[h];
#pragma unroll
            for (int a = 0; a < 32; a++)
                acc[a + 1] += Wa[(size_t)a * H_DIM + h];
        }
    }

#pragma unroll
    for (int a = 0; a < 33; a++)
#pragma unroll
        for (int off = 16; off > 0; off >>= 1)
            acc[a] += __shfl_xor_sync(0xFFFFFFFFu, acc[a], off);

    __shared__ float part[8][33];
    const int wid = threadIdx.x >> 5, lane = threadIdx.x & 31;
    if (lane == 0) {
#pragma unroll
        for (int a = 0; a < 33; a++) part[wid][a] = acc[a];
    }
    __syncthreads();

    if (threadIdx.x < 33) {
        const int a = threadIdx.x;
        float y = 0.0f;
#pragma unroll
        for (int w = 0; w < 8; w++) y += part[w][a];
        if (a == 0) {
            y = __fadd_rn(y, bc[0]);
            const float beta = *beta_critp;
            float mem = mem_crit[i];
            float reset = (mem > 1.0f) ? 1.0f : 0.0f;
            float m = __fsub_rn(fmaf(beta, mem, y), reset);
            out[OFF_VALUE + i] = (m > 1.0f) ? 1.0f : 0.0f;
            out[OFF_MCRIT + i] = m;
        } else {
            const int j = a - 1;
            y = __fadd_rn(y, ba[j]);
            const float beta = *beta_actp;
            float mem = mem_act[(size_t)i * A_DIM + j];
            float reset = (mem > 1.0f) ? 1.0f : 0.0f;
            float m = __fsub_rn(fmaf(beta, mem, y), reset);
            out[OFF_ACTION + (size_t)i * A_DIM + j] = (m > 1.0f) ? 1.0f : 0.0f;
            out[OFF_MACT + (size_t)i * A_DIM + j] = m;
        }
    }
}

// ---------------------------------------------------------------------------
extern "C" void kernel_launch(void* const* d_in, const int* in_sizes, int n_in,
                              void* d_out, int out_size)
{
    const float* inputs   = (const float*)d_in[0];
    const float* mem1     = (const float*)d_in[1];
    const float* mem2     = (const float*)d_in[2];
    const float* mem_act  = (const float*)d_in[3];
    const float* mem_crit = (const float*)d_in[4];
    const float* W1 = (const float*)d_in[5];
    const float* b1 = (const float*)d_in[6];
    const float* W2 = (const float*)d_in[7];
    const float* b2 = (const float*)d_in[8];
    const float* Wc = (const float*)d_in[9];
    const float* bc = (const float*)d_in[10];
    const float* Wa = (const float*)d_in[11];
    const float* ba = (const float*)d_in[12];
    const float* beta1     = (const float*)d_in[13];
    const float* beta2     = (const float*)d_in[14];
    const float* beta_crit = (const float*)d_in[15];
    const float* beta_act  = (const float*)d_in[16];
    float* out = (float*)d_out;

    float *cur1, *Pp, *S2;
    unsigned *S1bits, *cnt;
    unsigned long long* ent;
    cudaGetSymbolAddress((void**)&cur1, g_cur1);
    cudaGetSymbolAddress((void**)&S1bits, g_S1bits);
    cudaGetSymbolAddress((void**)&ent, g_ent);
    cudaGetSymbolAddress((void**)&cnt, g_cnt);
    cudaGetSymbolAddress((void**)&Pp, g_P);
    cudaGetSymbolAddress((void**)&S2, g_S2);

    static const int SMEM_BYTES = 513 * SM_STRIDE * 4;  // 135432
    cudaFuncSetAttribute(sgemm_sparse,
                         cudaFuncAttributeMaxDynamicSharedMemorySize,
                         SMEM_BYTES);

    // 1) cur1 = inputs @ W1^T + b1 (bit-exact chain)
    sgemm_nt<<<dim3(H_DIM / 128, MROWS / 128), 256>>>(
        inputs, W1, b1, cur1, MROWS, H_DIM, S_DIM);

    // 2) m1 scan -> spike bits + m1 final
    k_scan1<<<(unsigned)((NELEM + 255) / 256), 256>>>(
        cur1, mem1, beta1, out + OFF_M1, S1bits);

    // 3) index prepass v2: union lists with step-membership masks (+8 pads)
    k_index<<<(MROWS * 4) / 8, 256>>>(S1bits, ent, cnt);

    // 4) sparse big GEMM v4: fused bit-test, 24 warps, deep prefetch
    sgemm_sparse<<<dim3(H_DIM / 64, MROWS / 128, 4), 768, SMEM_BYTES>>>(
        W2, ent, cnt, Pp);

    // 5) m2 scan with fused slice merge + bias -> m2 final, S2 spikes
    k_scan2<<<(unsigned)((NELEM + 255) / 256), 256>>>(
        Pp, b2, mem2, beta2, out + OFF_M2, S2);

    // 6) heads
    k_heads<<<MROWS, 256>>>(S2, Wc, bc, Wa, ba, mem_act, mem_crit,
                            beta_crit, beta_act, out);
}